// round 1
// baseline (speedup 1.0000x reference)
#include <cuda_runtime.h>
#include <math.h>

#define B_ 4
#define T_ 1024
#define C_ 1024
#define H_ 16
#define D_ 64
#define M_ (B_*T_)      /* 4096 rows */
#define NQKV 3072
#define NFC  4096

// ---------------- scratch (__device__ globals: no allocation allowed) -------
__device__ float g_h  [M_*C_];                 // LN output (reused for LN2)
__device__ float g_q  [M_*C_];                 // (B,H,T,D)
__device__ float g_k  [M_*C_];
__device__ float g_v  [M_*C_];
__device__ float g_S  [(size_t)B_*H_*T_*T_];   // attention scores / probs (256MB)
__device__ float g_y  [M_*C_];                 // attn output (B,T,C)
__device__ float g_x2 [M_*C_];                 // masked residual after proj
__device__ float g_f  [(size_t)M_*NFC];        // gelu(fc) activations (64MB)
__device__ float g_imp[M_];                    // importance (B,T)
__device__ float g_msk[M_];                    // combined mask

// ---------------- small kernels --------------------------------------------
__global__ void zero_kernel(float* p, int n) {
    int i = blockIdx.x * 256 + threadIdx.x;
    if (i < n) p[i] = 0.f;
}

__global__ void mask_kernel(const float* __restrict__ imp,
                            const float* __restrict__ am,
                            const float* __restrict__ thr,
                            float* __restrict__ gmask,
                            float* __restrict__ outmask,
                            float* __restrict__ outloss) {
    int i = blockIdx.x * 256 + threadIdx.x;
    if (i < M_) {
        float pm = (imp[i] >= thr[0]) ? 1.f : 0.f;
        float cm = am[i] * pm;
        gmask[i]   = cm;
        outmask[i] = cm;
    }
    if (i == 0) outloss[0] = 0.f;
}

// ---------------- layer norm (one block per row) ----------------------------
__global__ void __launch_bounds__(256) ln_kernel(const float* __restrict__ x,
                                                 const float* __restrict__ w,
                                                 const float* __restrict__ b,
                                                 float* __restrict__ out) {
    int row = blockIdx.x;
    int tid = threadIdx.x;
    __shared__ float buf[C_];
    __shared__ float red[8];
    const float* xr = x + (size_t)row * C_;
    float s = 0.f;
    #pragma unroll
    for (int j = tid; j < C_; j += 256) { float v = xr[j]; buf[j] = v; s += v; }
    #pragma unroll
    for (int o = 16; o; o >>= 1) s += __shfl_down_sync(~0u, s, o);
    if ((tid & 31) == 0) red[tid >> 5] = s;
    __syncthreads();
    if (tid < 8) {
        s = red[tid];
        #pragma unroll
        for (int o = 4; o; o >>= 1) s += __shfl_down_sync(0xff, s, o);
        if (tid == 0) red[0] = s;
    }
    __syncthreads();
    float mu = red[0] * (1.f / C_);
    __syncthreads();
    float ss = 0.f;
    #pragma unroll
    for (int j = tid; j < C_; j += 256) { float d = buf[j] - mu; ss += d * d; }
    #pragma unroll
    for (int o = 16; o; o >>= 1) ss += __shfl_down_sync(~0u, ss, o);
    if ((tid & 31) == 0) red[tid >> 5] = ss;
    __syncthreads();
    if (tid < 8) {
        ss = red[tid];
        #pragma unroll
        for (int o = 4; o; o >>= 1) ss += __shfl_down_sync(0xff, ss, o);
        if (tid == 0) red[0] = ss;
    }
    __syncthreads();
    float rstd = rsqrtf(red[0] * (1.f / C_) + 1e-5f);
    float* orow = out + (size_t)row * C_;
    #pragma unroll
    for (int j = tid; j < C_; j += 256)
        orow[j] = (buf[j] - mu) * rstd * w[j] + b[j];
}

// ---------------- generic SGEMM 128x128x8, 8x8 micro, double buffered -------
// EPI: 0 = QKV scatter, 1 = proj (+x residual, *mask), 2 = GELU, 3 = residual
template<int EPI>
__global__ void __launch_bounds__(256) sgemm_kernel(
    const float* __restrict__ A, const float* __restrict__ W,
    const float* __restrict__ bias, const float* __restrict__ res,
    const float* __restrict__ mask, float* __restrict__ Cout,
    int M, int N, int K)
{
    __shared__ float As[2][8][128];
    __shared__ float Bs[2][8][128];
    int tid  = threadIdx.x;
    int row0 = blockIdx.y * 128, col0 = blockIdx.x * 128;
    int ar = tid >> 1,  ac = (tid & 1) * 4;     // A tile load: 128x8
    int br = tid >> 5,  bc = (tid & 31) * 4;    // B tile load: 8x128
    int ty = tid >> 4,  tx = tid & 15;

    const float* Aptr = A + (size_t)(row0 + ar) * K + ac;
    float acc[8][8] = {};
    int nk = K >> 3;

    // prologue: tile 0 -> buffer 0
    {
        float4 pa = *(const float4*)Aptr;
        float4 pb = *(const float4*)(W + (size_t)br * N + col0 + bc);
        As[0][ac+0][ar] = pa.x; As[0][ac+1][ar] = pa.y;
        As[0][ac+2][ar] = pa.z; As[0][ac+3][ar] = pa.w;
        *(float4*)&Bs[0][br][bc] = pb;
    }
    __syncthreads();

    for (int kt = 0; kt < nk; kt++) {
        int cur = kt & 1;
        float4 na, nb;
        if (kt + 1 < nk) {
            na = *(const float4*)(Aptr + (kt + 1) * 8);
            nb = *(const float4*)(W + (size_t)((kt + 1) * 8 + br) * N + col0 + bc);
        }
        #pragma unroll
        for (int k = 0; k < 8; k++) {
            float a[8], b[8];
            *(float4*)(a)     = *(const float4*)&As[cur][k][ty * 8];
            *(float4*)(a + 4) = *(const float4*)&As[cur][k][ty * 8 + 4];
            *(float4*)(b)     = *(const float4*)&Bs[cur][k][tx * 8];
            *(float4*)(b + 4) = *(const float4*)&Bs[cur][k][tx * 8 + 4];
            #pragma unroll
            for (int i = 0; i < 8; i++)
                #pragma unroll
                for (int j = 0; j < 8; j++)
                    acc[i][j] += a[i] * b[j];
        }
        if (kt + 1 < nk) {
            int nxt = 1 - cur;
            As[nxt][ac+0][ar] = na.x; As[nxt][ac+1][ar] = na.y;
            As[nxt][ac+2][ar] = na.z; As[nxt][ac+3][ar] = na.w;
            *(float4*)&Bs[nxt][br][bc] = nb;
            __syncthreads();
        }
    }

    // ---- epilogues ----
    #pragma unroll
    for (int i = 0; i < 8; i++) {
        int ig = row0 + ty * 8 + i;
        if (EPI == 0) {   // QKV scatter: col -> (part, head, dim); row -> (b, t)
            int bq = ig >> 10, t = ig & 1023;
            #pragma unroll
            for (int j = 0; j < 8; j++) {
                int jg = col0 + tx * 8 + j;
                int part = jg >> 10;
                int c = jg & 1023;
                int h = c >> 6, d = c & 63;
                float val = acc[i][j] + bias[jg];
                float* dst = (part == 0) ? g_q : (part == 1) ? g_k : g_v;
                dst[((size_t)(bq * H_ + h) * T_ + t) * D_ + d] = val;
            }
        } else if (EPI == 1) {  // proj: (x + y@W + b) * mask[row]
            float mrow = mask[ig];
            #pragma unroll
            for (int j = 0; j < 8; j++) {
                int jg = col0 + tx * 8 + j;
                float val = (res[(size_t)ig * N + jg] + acc[i][j] + bias[jg]) * mrow;
                Cout[(size_t)ig * N + jg] = val;
            }
        } else if (EPI == 2) {  // exact GELU
            #pragma unroll
            for (int j = 0; j < 8; j++) {
                int jg = col0 + tx * 8 + j;
                float v = acc[i][j] + bias[jg];
                Cout[(size_t)ig * N + jg] = 0.5f * v * (1.f + erff(v * 0.70710678118654752f));
            }
        } else {                // residual
            #pragma unroll
            for (int j = 0; j < 8; j++) {
                int jg = col0 + tx * 8 + j;
                Cout[(size_t)ig * N + jg] = res[(size_t)ig * N + jg] + acc[i][j] + bias[jg];
            }
        }
    }
}

// ---------------- attention scores: S = q @ k^T * scale (lower-tri tiles) ---
__global__ void __launch_bounds__(256) scores_kernel(const float* __restrict__ q,
                                                     const float* __restrict__ k,
                                                     float* __restrict__ S) {
    int kt = blockIdx.x, qt = blockIdx.y, bh = blockIdx.z;
    if (kt > qt) return;
    __shared__ float Qs[64][64];   // [d][m]
    __shared__ float Ks[64][64];   // [d][n]
    int tid = threadIdx.x;
    const float* qb = q + (size_t)bh * T_ * D_ + (size_t)qt * 64 * D_;
    const float* kb = k + (size_t)bh * T_ * D_ + (size_t)kt * 64 * D_;
    int r = tid >> 4, c = (tid & 15) * 4;
    #pragma unroll
    for (int it = 0; it < 4; it++) {
        int row = it * 16 + r;
        float4 vq = *(const float4*)(qb + row * D_ + c);
        Qs[c+0][row] = vq.x; Qs[c+1][row] = vq.y; Qs[c+2][row] = vq.z; Qs[c+3][row] = vq.w;
        float4 vk = *(const float4*)(kb + row * D_ + c);
        Ks[c+0][row] = vk.x; Ks[c+1][row] = vk.y; Ks[c+2][row] = vk.z; Ks[c+3][row] = vk.w;
    }
    __syncthreads();
    int ty = tid >> 4, tx = tid & 15;
    float acc[4][4] = {};
    #pragma unroll
    for (int d = 0; d < 64; d++) {
        float a[4], b[4];
        *(float4*)a = *(const float4*)&Qs[d][ty * 4];
        *(float4*)b = *(const float4*)&Ks[d][tx * 4];
        #pragma unroll
        for (int i = 0; i < 4; i++)
            #pragma unroll
            for (int j = 0; j < 4; j++)
                acc[i][j] += a[i] * b[j];
    }
    float* Sb = S + (size_t)bh * T_ * T_ + (size_t)(qt * 64) * T_ + kt * 64;
    #pragma unroll
    for (int i = 0; i < 4; i++)
        #pragma unroll
        for (int j = 0; j < 4; j++)
            Sb[(size_t)(ty * 4 + i) * T_ + tx * 4 + j] = acc[i][j] * 0.125f;
}

// ---------------- softmax rows (causal+keymask) + column-sum importance -----
__global__ void __launch_bounds__(256) softmax_kernel(float* __restrict__ S,
                                                      const float* __restrict__ am,
                                                      float* __restrict__ imp) {
    int qt = blockIdx.x, bh = blockIdx.y;
    int b = bh >> 4;
    int tid = threadIdx.x;
    __shared__ float colsum[T_];
    __shared__ float red[8];
    #pragma unroll
    for (int j = tid; j < T_; j += 256) colsum[j] = 0.f;
    const float* amb = am + b * T_;
    float* base = S + (size_t)bh * T_ * T_ + (size_t)qt * 16 * T_;

    for (int r = 0; r < 16; r++) {
        int qg = qt * 16 + r;
        float* row = base + (size_t)r * T_;
        // max over valid keys
        float lm = -1e30f;
        for (int j = tid; j <= qg; j += 256)
            if (amb[j] != 0.f) lm = fmaxf(lm, row[j]);
        #pragma unroll
        for (int o = 16; o; o >>= 1) lm = fmaxf(lm, __shfl_down_sync(~0u, lm, o));
        if ((tid & 31) == 0) red[tid >> 5] = lm;
        __syncthreads();
        if (tid < 8) {
            lm = red[tid];
            #pragma unroll
            for (int o = 4; o; o >>= 1) lm = fmaxf(lm, __shfl_down_sync(0xff, lm, o));
            if (tid == 0) red[0] = lm;
        }
        __syncthreads();
        float m = red[0];
        __syncthreads();
        // exp + sum (write unnormalized back; invalid -> 0)
        float ls = 0.f;
        for (int j = tid; j < T_; j += 256) {
            float e = (j <= qg && amb[j] != 0.f) ? __expf(row[j] - m) : 0.f;
            row[j] = e;
            ls += e;
        }
        #pragma unroll
        for (int o = 16; o; o >>= 1) ls += __shfl_down_sync(~0u, ls, o);
        if ((tid & 31) == 0) red[tid >> 5] = ls;
        __syncthreads();
        if (tid < 8) {
            ls = red[tid];
            #pragma unroll
            for (int o = 4; o; o >>= 1) ls += __shfl_down_sync(0xff, ls, o);
            if (tid == 0) red[0] = ls;
        }
        __syncthreads();
        float inv = 1.f / red[0];
        __syncthreads();
        for (int j = tid; j < T_; j += 256) {
            float a = row[j] * inv;
            row[j] = a;
            colsum[j] += a;     // per-thread-owned slots (j % 256 == tid)
        }
    }
    __syncthreads();
    for (int j = tid; j < T_; j += 256)
        atomicAdd(&imp[b * T_ + j], colsum[j] * (1.f / (H_ * T_)));
}

// ---------------- y = att @ v  (causally trimmed k-loop) --------------------
__global__ void __launch_bounds__(256) attv_kernel(const float* __restrict__ S,
                                                   const float* __restrict__ v,
                                                   float* __restrict__ y) {
    int qt = blockIdx.x, bh = blockIdx.y;
    int b = bh >> 4, h = bh & 15;
    __shared__ float As[16][64];  // [k][m]
    __shared__ float Vs[16][64];  // [k][n]
    int tid = threadIdx.x;
    int q0 = qt * 64;
    const float* Sb = S + (size_t)bh * T_ * T_ + (size_t)q0 * T_;
    const float* vb = v + (size_t)bh * T_ * D_;
    int arow = tid >> 2, acol = (tid & 3) * 4;
    int vrow = tid >> 4, vcol = (tid & 15) * 4;
    int ty = tid >> 4, tx = tid & 15;
    float acc[4][4] = {};
    int nkt = (qt + 1) * 4;   // tiles of 16 keys, up to causal limit
    for (int kt = 0; kt < nkt; kt++) {
        float4 va = *(const float4*)(Sb + (size_t)arow * T_ + kt * 16 + acol);
        float4 vv = *(const float4*)(vb + (size_t)(kt * 16 + vrow) * D_ + vcol);
        __syncthreads();
        As[acol+0][arow] = va.x; As[acol+1][arow] = va.y;
        As[acol+2][arow] = va.z; As[acol+3][arow] = va.w;
        *(float4*)&Vs[vrow][vcol] = vv;
        __syncthreads();
        #pragma unroll
        for (int k = 0; k < 16; k++) {
            float a[4], bb[4];
            *(float4*)a  = *(const float4*)&As[k][ty * 4];
            *(float4*)bb = *(const float4*)&Vs[k][tx * 4];
            #pragma unroll
            for (int i = 0; i < 4; i++)
                #pragma unroll
                for (int j = 0; j < 4; j++)
                    acc[i][j] += a[i] * bb[j];
        }
    }
    #pragma unroll
    for (int i = 0; i < 4; i++) {
        int t = q0 + ty * 4 + i;
        #pragma unroll
        for (int j = 0; j < 4; j++)
            y[((size_t)(b * T_ + t)) * C_ + h * 64 + tx * 4 + j] = acc[i][j];
    }
}

// ---------------- launch ----------------------------------------------------
extern "C" void kernel_launch(void* const* d_in, const int* in_sizes, int n_in,
                              void* d_out, int out_size) {
    const float* x     = (const float*)d_in[0];
    const float* am    = (const float*)d_in[1];
    const float* ln1w  = (const float*)d_in[2];
    const float* ln1b  = (const float*)d_in[3];
    const float* wattn = (const float*)d_in[4];
    const float* battn = (const float*)d_in[5];
    const float* wproj = (const float*)d_in[6];
    const float* bproj = (const float*)d_in[7];
    const float* thr   = (const float*)d_in[8];
    const float* ln2w  = (const float*)d_in[9];
    const float* ln2b  = (const float*)d_in[10];
    const float* wfc   = (const float*)d_in[11];
    const float* bfc   = (const float*)d_in[12];
    const float* wfc2  = (const float*)d_in[13];
    const float* bfc2  = (const float*)d_in[14];

    float* out      = (float*)d_out;
    float* out_x    = out;                       // (B,T,C)
    float* out_mask = out + out_size - 1 - M_;   // (B,T)
    float* out_loss = out + out_size - 1;        // scalar

    float *ph, *pq, *pk, *pv, *pS, *py, *px2, *pf, *pimp, *pmsk;
    cudaGetSymbolAddress((void**)&ph,   g_h);
    cudaGetSymbolAddress((void**)&pq,   g_q);
    cudaGetSymbolAddress((void**)&pk,   g_k);
    cudaGetSymbolAddress((void**)&pv,   g_v);
    cudaGetSymbolAddress((void**)&pS,   g_S);
    cudaGetSymbolAddress((void**)&py,   g_y);
    cudaGetSymbolAddress((void**)&px2,  g_x2);
    cudaGetSymbolAddress((void**)&pf,   g_f);
    cudaGetSymbolAddress((void**)&pimp, g_imp);
    cudaGetSymbolAddress((void**)&pmsk, g_msk);

    zero_kernel<<<16, 256>>>(pimp, M_);
    ln_kernel<<<M_, 256>>>(x, ln1w, ln1b, ph);
    sgemm_kernel<0><<<dim3(NQKV/128, M_/128), 256>>>(ph, wattn, battn,
                                                     nullptr, nullptr, nullptr,
                                                     M_, NQKV, C_);
    scores_kernel<<<dim3(16, 16, B_*H_), 256>>>(pq, pk, pS);
    softmax_kernel<<<dim3(T_/16, B_*H_), 256>>>(pS, am, pimp);
    mask_kernel<<<16, 256>>>(pimp, am, thr, pmsk, out_mask, out_loss);
    attv_kernel<<<dim3(T_/64, B_*H_), 256>>>(pS, pv, py);
    sgemm_kernel<1><<<dim3(C_/128, M_/128), 256>>>(py, wproj, bproj,
                                                   x, pmsk, px2,
                                                   M_, C_, C_);
    ln_kernel<<<M_, 256>>>(px2, ln2w, ln2b, ph);
    sgemm_kernel<2><<<dim3(NFC/128, M_/128), 256>>>(ph, wfc, bfc,
                                                    nullptr, nullptr, pf,
                                                    M_, NFC, C_);
    sgemm_kernel<3><<<dim3(C_/128, M_/128), 256>>>(pf, wfc2, bfc2,
                                                   px2, nullptr, out_x,
                                                   M_, C_, NFC);
}

// round 2
// speedup vs baseline: 2.0535x; 2.0535x over previous
#include <cuda_runtime.h>
#include <math.h>
#include <stdint.h>

#define B_ 4
#define T_ 1024
#define C_ 1024
#define H_ 16
#define D_ 64
#define M_ (B_*T_)      /* 4096 rows */
#define NQKV 3072
#define NFC  4096

// ---------------- scratch (__device__ globals: no allocation allowed) -------
__device__ float g_h  [M_*C_];                 // LN output (reused for LN2)
__device__ float g_q  [M_*C_];                 // (B,H,T,D)
__device__ float g_k  [M_*C_];
__device__ float g_v  [M_*C_];
__device__ float g_S  [(size_t)B_*H_*T_*T_];   // attention scores / probs (256MB)
__device__ float g_y  [M_*C_];                 // attn output (B,T,C)
__device__ float g_x2 [M_*C_];                 // masked residual after proj
__device__ float g_f  [(size_t)M_*NFC];        // gelu(fc) activations (64MB)
__device__ float g_imp[M_];                    // importance (B,T)
__device__ float g_msk[M_];                    // combined mask

// ---------------- helpers ---------------------------------------------------
__device__ __forceinline__ float to_tf32(float x) {
    uint32_t u;
    asm("cvt.rna.tf32.f32 %0, %1;" : "=r"(u) : "f"(x));
    return __uint_as_float(u);
}

__device__ __forceinline__ void mma_tf32(float c[4], const float a[4], const float b[2]) {
    asm volatile(
        "mma.sync.aligned.m16n8k8.row.col.f32.tf32.tf32.f32 "
        "{%0,%1,%2,%3}, {%4,%5,%6,%7}, {%8,%9}, {%0,%1,%2,%3};"
        : "+f"(c[0]), "+f"(c[1]), "+f"(c[2]), "+f"(c[3])
        : "r"(__float_as_uint(a[0])), "r"(__float_as_uint(a[1])),
          "r"(__float_as_uint(a[2])), "r"(__float_as_uint(a[3])),
          "r"(__float_as_uint(b[0])), "r"(__float_as_uint(b[1])));
}

// ---------------- small kernels --------------------------------------------
__global__ void zero_kernel(float* p, int n) {
    int i = blockIdx.x * 256 + threadIdx.x;
    if (i < n) p[i] = 0.f;
}

__global__ void mask_kernel(const float* __restrict__ imp,
                            const float* __restrict__ am,
                            const float* __restrict__ thr,
                            float* __restrict__ gmask,
                            float* __restrict__ outmask,
                            float* __restrict__ outloss) {
    int i = blockIdx.x * 256 + threadIdx.x;
    if (i < M_) {
        float pm = (imp[i] >= thr[0]) ? 1.f : 0.f;
        float cm = am[i] * pm;
        gmask[i]   = cm;
        outmask[i] = cm;
    }
    if (i == 0) outloss[0] = 0.f;
}

// ---------------- layer norm (one block per row) ----------------------------
__global__ void __launch_bounds__(256) ln_kernel(const float* __restrict__ x,
                                                 const float* __restrict__ w,
                                                 const float* __restrict__ b,
                                                 float* __restrict__ out) {
    int row = blockIdx.x;
    int tid = threadIdx.x;
    __shared__ float buf[C_];
    __shared__ float red[8];
    const float* xr = x + (size_t)row * C_;
    float s = 0.f;
    #pragma unroll
    for (int j = tid; j < C_; j += 256) { float v = xr[j]; buf[j] = v; s += v; }
    #pragma unroll
    for (int o = 16; o; o >>= 1) s += __shfl_down_sync(~0u, s, o);
    if ((tid & 31) == 0) red[tid >> 5] = s;
    __syncthreads();
    if (tid < 8) {
        s = red[tid];
        #pragma unroll
        for (int o = 4; o; o >>= 1) s += __shfl_down_sync(0xff, s, o);
        if (tid == 0) red[0] = s;
    }
    __syncthreads();
    float mu = red[0] * (1.f / C_);
    __syncthreads();
    float ss = 0.f;
    #pragma unroll
    for (int j = tid; j < C_; j += 256) { float d = buf[j] - mu; ss += d * d; }
    #pragma unroll
    for (int o = 16; o; o >>= 1) ss += __shfl_down_sync(~0u, ss, o);
    if ((tid & 31) == 0) red[tid >> 5] = ss;
    __syncthreads();
    if (tid < 8) {
        ss = red[tid];
        #pragma unroll
        for (int o = 4; o; o >>= 1) ss += __shfl_down_sync(0xff, ss, o);
        if (tid == 0) red[0] = ss;
    }
    __syncthreads();
    float rstd = rsqrtf(red[0] * (1.f / C_) + 1e-5f);
    float* orow = out + (size_t)row * C_;
    #pragma unroll
    for (int j = tid; j < C_; j += 256)
        orow[j] = (buf[j] - mu) * rstd * w[j] + b[j];
}

// ---------------- tf32 tensor-core GEMM: 128x128x16, 8 warps (2x4) ---------
// Each warp: 64x32 tile = 4x4 fragments of m16n8k8.
// EPI: 0 = QKV scatter, 1 = proj (+x residual, *mask), 2 = GELU, 3 = residual
#define SPAD 136   /* 128 + 8 floats: makes fragment LDS bank-exact */

template<int EPI>
__global__ void __launch_bounds__(256, 2) tgemm_kernel(
    const float* __restrict__ A, const float* __restrict__ W,
    const float* __restrict__ bias, const float* __restrict__ res,
    const float* __restrict__ mask, float* __restrict__ Cout,
    int M, int N, int K)
{
    __shared__ float As[2][16][SPAD];   // [k][m]
    __shared__ float Bs[2][16][SPAD];   // [k][n]
    int tid  = threadIdx.x;
    int lane = tid & 31;
    int wid  = tid >> 5;
    int warpM = wid >> 2, warpN = wid & 3;      // 2 x 4 warps
    int g  = lane >> 2, tg = lane & 3;
    int row0 = blockIdx.y * 128, col0 = blockIdx.x * 128;

    // A tile loads: 128 rows x 16 k = 512 float4; each thread 2.
    int aRow0 = tid >> 2,         aK0 = (tid & 3) << 2;
    int aRow1 = (tid + 256) >> 2, aK1 = aK0;
    // B tile loads: 16 rows x 128 cols = 512 float4; each thread 2.
    int bRow0 = tid >> 5,       bCol0 = (tid & 31) << 2;
    int bRow1 = bRow0 + 8,      bCol1 = bCol0;

    const float* aP0 = A + (size_t)(row0 + aRow0) * K + aK0;
    const float* aP1 = A + (size_t)(row0 + aRow1) * K + aK1;

    float acc[4][4][4] = {};
    int nk = K >> 4;

    // prologue: stage 0 -> buffer 0
    {
        float4 va0 = *(const float4*)aP0;
        float4 va1 = *(const float4*)aP1;
        float4 vb0 = *(const float4*)(W + (size_t)bRow0 * N + col0 + bCol0);
        float4 vb1 = *(const float4*)(W + (size_t)bRow1 * N + col0 + bCol1);
        As[0][aK0+0][aRow0] = to_tf32(va0.x); As[0][aK0+1][aRow0] = to_tf32(va0.y);
        As[0][aK0+2][aRow0] = to_tf32(va0.z); As[0][aK0+3][aRow0] = to_tf32(va0.w);
        As[0][aK1+0][aRow1] = to_tf32(va1.x); As[0][aK1+1][aRow1] = to_tf32(va1.y);
        As[0][aK1+2][aRow1] = to_tf32(va1.z); As[0][aK1+3][aRow1] = to_tf32(va1.w);
        Bs[0][bRow0][bCol0+0] = to_tf32(vb0.x); Bs[0][bRow0][bCol0+1] = to_tf32(vb0.y);
        Bs[0][bRow0][bCol0+2] = to_tf32(vb0.z); Bs[0][bRow0][bCol0+3] = to_tf32(vb0.w);
        Bs[0][bRow1][bCol1+0] = to_tf32(vb1.x); Bs[0][bRow1][bCol1+1] = to_tf32(vb1.y);
        Bs[0][bRow1][bCol1+2] = to_tf32(vb1.z); Bs[0][bRow1][bCol1+3] = to_tf32(vb1.w);
    }
    __syncthreads();

    int mBase = warpM * 64;
    int nBase = warpN * 32;

    for (int kt = 0; kt < nk; kt++) {
        int cur = kt & 1;
        float4 va0, va1, vb0, vb1;
        if (kt + 1 < nk) {
            int k0 = (kt + 1) * 16;
            va0 = *(const float4*)(aP0 + k0);
            va1 = *(const float4*)(aP1 + k0);
            vb0 = *(const float4*)(W + (size_t)(k0 + bRow0) * N + col0 + bCol0);
            vb1 = *(const float4*)(W + (size_t)(k0 + bRow1) * N + col0 + bCol1);
        }
        #pragma unroll
        for (int kk = 0; kk < 16; kk += 8) {
            float a[4][4], b[4][2];
            #pragma unroll
            for (int mi = 0; mi < 4; mi++) {
                int m = mBase + mi * 16 + g;
                a[mi][0] = As[cur][kk + tg    ][m];
                a[mi][1] = As[cur][kk + tg    ][m + 8];
                a[mi][2] = As[cur][kk + tg + 4][m];
                a[mi][3] = As[cur][kk + tg + 4][m + 8];
            }
            #pragma unroll
            for (int ni = 0; ni < 4; ni++) {
                int n = nBase + ni * 8 + g;
                b[ni][0] = Bs[cur][kk + tg    ][n];
                b[ni][1] = Bs[cur][kk + tg + 4][n];
            }
            #pragma unroll
            for (int mi = 0; mi < 4; mi++)
                #pragma unroll
                for (int ni = 0; ni < 4; ni++)
                    mma_tf32(acc[mi][ni], a[mi], b[ni]);
        }
        if (kt + 1 < nk) {
            int nxt = 1 - cur;
            As[nxt][aK0+0][aRow0] = to_tf32(va0.x); As[nxt][aK0+1][aRow0] = to_tf32(va0.y);
            As[nxt][aK0+2][aRow0] = to_tf32(va0.z); As[nxt][aK0+3][aRow0] = to_tf32(va0.w);
            As[nxt][aK1+0][aRow1] = to_tf32(va1.x); As[nxt][aK1+1][aRow1] = to_tf32(va1.y);
            As[nxt][aK1+2][aRow1] = to_tf32(va1.z); As[nxt][aK1+3][aRow1] = to_tf32(va1.w);
            Bs[nxt][bRow0][bCol0+0] = to_tf32(vb0.x); Bs[nxt][bRow0][bCol0+1] = to_tf32(vb0.y);
            Bs[nxt][bRow0][bCol0+2] = to_tf32(vb0.z); Bs[nxt][bRow0][bCol0+3] = to_tf32(vb0.w);
            Bs[nxt][bRow1][bCol1+0] = to_tf32(vb1.x); Bs[nxt][bRow1][bCol1+1] = to_tf32(vb1.y);
            Bs[nxt][bRow1][bCol1+2] = to_tf32(vb1.z); Bs[nxt][bRow1][bCol1+3] = to_tf32(vb1.w);
            __syncthreads();
        }
    }

    // ---- epilogue ----
    #pragma unroll
    for (int mi = 0; mi < 4; mi++) {
        #pragma unroll
        for (int half = 0; half < 2; half++) {
            int ig = row0 + mBase + mi * 16 + g + half * 8;
            #pragma unroll
            for (int ni = 0; ni < 4; ni++) {
                float v0 = acc[mi][ni][2 * half + 0];
                float v1 = acc[mi][ni][2 * half + 1];
                int jg = col0 + nBase + ni * 8 + tg * 2;
                if (EPI == 0) {        // QKV scatter
                    int bq = ig >> 10, t = ig & 1023;
                    #pragma unroll
                    for (int e = 0; e < 2; e++) {
                        int j = jg + e;
                        int part = j >> 10;
                        int c = j & 1023;
                        int h = c >> 6, d = c & 63;
                        float val = (e ? v1 : v0) + bias[j];
                        float* dst = (part == 0) ? g_q : (part == 1) ? g_k : g_v;
                        dst[((size_t)(bq * H_ + h) * T_ + t) * D_ + d] = val;
                    }
                } else if (EPI == 1) { // proj: (x + y@W + b) * mask[row]
                    float mrow = mask[ig];
                    Cout[(size_t)ig * N + jg]     = (res[(size_t)ig * N + jg]     + v0 + bias[jg])     * mrow;
                    Cout[(size_t)ig * N + jg + 1] = (res[(size_t)ig * N + jg + 1] + v1 + bias[jg + 1]) * mrow;
                } else if (EPI == 2) { // exact GELU
                    float a0 = v0 + bias[jg], a1 = v1 + bias[jg + 1];
                    Cout[(size_t)ig * N + jg]     = 0.5f * a0 * (1.f + erff(a0 * 0.70710678118654752f));
                    Cout[(size_t)ig * N + jg + 1] = 0.5f * a1 * (1.f + erff(a1 * 0.70710678118654752f));
                } else {               // residual
                    Cout[(size_t)ig * N + jg]     = res[(size_t)ig * N + jg]     + v0 + bias[jg];
                    Cout[(size_t)ig * N + jg + 1] = res[(size_t)ig * N + jg + 1] + v1 + bias[jg + 1];
                }
            }
        }
    }
}

// ---------------- attention scores: S = q @ k^T * scale (lower-tri tiles) ---
__global__ void __launch_bounds__(256) scores_kernel(const float* __restrict__ q,
                                                     const float* __restrict__ k,
                                                     float* __restrict__ S) {
    int kt = blockIdx.x, qt = blockIdx.y, bh = blockIdx.z;
    if (kt > qt) return;
    __shared__ float Qs[64][64];   // [d][m]
    __shared__ float Ks[64][64];   // [d][n]
    int tid = threadIdx.x;
    const float* qb = q + (size_t)bh * T_ * D_ + (size_t)qt * 64 * D_;
    const float* kb = k + (size_t)bh * T_ * D_ + (size_t)kt * 64 * D_;
    int r = tid >> 4, c = (tid & 15) * 4;
    #pragma unroll
    for (int it = 0; it < 4; it++) {
        int row = it * 16 + r;
        float4 vq = *(const float4*)(qb + row * D_ + c);
        Qs[c+0][row] = vq.x; Qs[c+1][row] = vq.y; Qs[c+2][row] = vq.z; Qs[c+3][row] = vq.w;
        float4 vk = *(const float4*)(kb + row * D_ + c);
        Ks[c+0][row] = vk.x; Ks[c+1][row] = vk.y; Ks[c+2][row] = vk.z; Ks[c+3][row] = vk.w;
    }
    __syncthreads();
    int ty = tid >> 4, tx = tid & 15;
    float acc[4][4] = {};
    #pragma unroll
    for (int d = 0; d < 64; d++) {
        float a[4], b[4];
        *(float4*)a = *(const float4*)&Qs[d][ty * 4];
        *(float4*)b = *(const float4*)&Ks[d][tx * 4];
        #pragma unroll
        for (int i = 0; i < 4; i++)
            #pragma unroll
            for (int j = 0; j < 4; j++)
                acc[i][j] += a[i] * b[j];
    }
    float* Sb = S + (size_t)bh * T_ * T_ + (size_t)(qt * 64) * T_ + kt * 64;
    #pragma unroll
    for (int i = 0; i < 4; i++)
        #pragma unroll
        for (int j = 0; j < 4; j++)
            Sb[(size_t)(ty * 4 + i) * T_ + tx * 4 + j] = acc[i][j] * 0.125f;
}

// ---------------- softmax rows (causal+keymask) + column-sum importance -----
__global__ void __launch_bounds__(256) softmax_kernel(float* __restrict__ S,
                                                      const float* __restrict__ am,
                                                      float* __restrict__ imp) {
    int qt = blockIdx.x, bh = blockIdx.y;
    int b = bh >> 4;
    int tid = threadIdx.x;
    __shared__ float colsum[T_];
    __shared__ float red[8];
    #pragma unroll
    for (int j = tid; j < T_; j += 256) colsum[j] = 0.f;
    const float* amb = am + b * T_;
    float* base = S + (size_t)bh * T_ * T_ + (size_t)qt * 16 * T_;

    for (int r = 0; r < 16; r++) {
        int qg = qt * 16 + r;
        float* row = base + (size_t)r * T_;
        float lm = -1e30f;
        for (int j = tid; j <= qg; j += 256)
            if (amb[j] != 0.f) lm = fmaxf(lm, row[j]);
        #pragma unroll
        for (int o = 16; o; o >>= 1) lm = fmaxf(lm, __shfl_down_sync(~0u, lm, o));
        if ((tid & 31) == 0) red[tid >> 5] = lm;
        __syncthreads();
        if (tid < 8) {
            lm = red[tid];
            #pragma unroll
            for (int o = 4; o; o >>= 1) lm = fmaxf(lm, __shfl_down_sync(0xff, lm, o));
            if (tid == 0) red[0] = lm;
        }
        __syncthreads();
        float m = red[0];
        __syncthreads();
        float ls = 0.f;
        for (int j = tid; j < T_; j += 256) {
            float e = (j <= qg && amb[j] != 0.f) ? __expf(row[j] - m) : 0.f;
            row[j] = e;
            ls += e;
        }
        #pragma unroll
        for (int o = 16; o; o >>= 1) ls += __shfl_down_sync(~0u, ls, o);
        if ((tid & 31) == 0) red[tid >> 5] = ls;
        __syncthreads();
        if (tid < 8) {
            ls = red[tid];
            #pragma unroll
            for (int o = 4; o; o >>= 1) ls += __shfl_down_sync(0xff, ls, o);
            if (tid == 0) red[0] = ls;
        }
        __syncthreads();
        float inv = 1.f / red[0];
        __syncthreads();
        for (int j = tid; j < T_; j += 256) {
            float a = row[j] * inv;
            row[j] = a;
            colsum[j] += a;
        }
    }
    __syncthreads();
    for (int j = tid; j < T_; j += 256)
        atomicAdd(&imp[b * T_ + j], colsum[j] * (1.f / (H_ * T_)));
}

// ---------------- y = att @ v  (causally trimmed k-loop) --------------------
__global__ void __launch_bounds__(256) attv_kernel(const float* __restrict__ S,
                                                   const float* __restrict__ v,
                                                   float* __restrict__ y) {
    int qt = blockIdx.x, bh = blockIdx.y;
    int b = bh >> 4, h = bh & 15;
    __shared__ float As[16][64];
    __shared__ float Vs[16][64];
    int tid = threadIdx.x;
    int q0 = qt * 64;
    const float* Sb = S + (size_t)bh * T_ * T_ + (size_t)q0 * T_;
    const float* vb = v + (size_t)bh * T_ * D_;
    int arow = tid >> 2, acol = (tid & 3) * 4;
    int vrow = tid >> 4, vcol = (tid & 15) * 4;
    int ty = tid >> 4, tx = tid & 15;
    float acc[4][4] = {};
    int nkt = (qt + 1) * 4;
    for (int kt = 0; kt < nkt; kt++) {
        float4 va = *(const float4*)(Sb + (size_t)arow * T_ + kt * 16 + acol);
        float4 vv = *(const float4*)(vb + (size_t)(kt * 16 + vrow) * D_ + vcol);
        __syncthreads();
        As[acol+0][arow] = va.x; As[acol+1][arow] = va.y;
        As[acol+2][arow] = va.z; As[acol+3][arow] = va.w;
        *(float4*)&Vs[vrow][vcol] = vv;
        __syncthreads();
        #pragma unroll
        for (int k = 0; k < 16; k++) {
            float a[4], bb[4];
            *(float4*)a  = *(const float4*)&As[k][ty * 4];
            *(float4*)bb = *(const float4*)&Vs[k][tx * 4];
            #pragma unroll
            for (int i = 0; i < 4; i++)
                #pragma unroll
                for (int j = 0; j < 4; j++)
                    acc[i][j] += a[i] * bb[j];
        }
    }
    #pragma unroll
    for (int i = 0; i < 4; i++) {
        int t = q0 + ty * 4 + i;
        #pragma unroll
        for (int j = 0; j < 4; j++)
            y[((size_t)(b * T_ + t)) * C_ + h * 64 + tx * 4 + j] = acc[i][j];
    }
}

// ---------------- launch ----------------------------------------------------
extern "C" void kernel_launch(void* const* d_in, const int* in_sizes, int n_in,
                              void* d_out, int out_size) {
    const float* x     = (const float*)d_in[0];
    const float* am    = (const float*)d_in[1];
    const float* ln1w  = (const float*)d_in[2];
    const float* ln1b  = (const float*)d_in[3];
    const float* wattn = (const float*)d_in[4];
    const float* battn = (const float*)d_in[5];
    const float* wproj = (const float*)d_in[6];
    const float* bproj = (const float*)d_in[7];
    const float* thr   = (const float*)d_in[8];
    const float* ln2w  = (const float*)d_in[9];
    const float* ln2b  = (const float*)d_in[10];
    const float* wfc   = (const float*)d_in[11];
    const float* bfc   = (const float*)d_in[12];
    const float* wfc2  = (const float*)d_in[13];
    const float* bfc2  = (const float*)d_in[14];

    float* out      = (float*)d_out;
    float* out_x    = out;                       // (B,T,C)
    float* out_mask = out + out_size - 1 - M_;   // (B,T)
    float* out_loss = out + out_size - 1;        // scalar

    float *ph, *pq, *pk, *pv, *pS, *py, *px2, *pf, *pimp, *pmsk;
    cudaGetSymbolAddress((void**)&ph,   g_h);
    cudaGetSymbolAddress((void**)&pq,   g_q);
    cudaGetSymbolAddress((void**)&pk,   g_k);
    cudaGetSymbolAddress((void**)&pv,   g_v);
    cudaGetSymbolAddress((void**)&pS,   g_S);
    cudaGetSymbolAddress((void**)&py,   g_y);
    cudaGetSymbolAddress((void**)&px2,  g_x2);
    cudaGetSymbolAddress((void**)&pf,   g_f);
    cudaGetSymbolAddress((void**)&pimp, g_imp);
    cudaGetSymbolAddress((void**)&pmsk, g_msk);

    zero_kernel<<<16, 256>>>(pimp, M_);
    ln_kernel<<<M_, 256>>>(x, ln1w, ln1b, ph);
    tgemm_kernel<0><<<dim3(NQKV/128, M_/128), 256>>>(ph, wattn, battn,
                                                     nullptr, nullptr, nullptr,
                                                     M_, NQKV, C_);
    scores_kernel<<<dim3(16, 16, B_*H_), 256>>>(pq, pk, pS);
    softmax_kernel<<<dim3(T_/16, B_*H_), 256>>>(pS, am, pimp);
    mask_kernel<<<16, 256>>>(pimp, am, thr, pmsk, out_mask, out_loss);
    attv_kernel<<<dim3(T_/64, B_*H_), 256>>>(pS, pv, py);
    tgemm_kernel<1><<<dim3(C_/128, M_/128), 256>>>(py, wproj, bproj,
                                                   x, pmsk, px2,
                                                   M_, C_, C_);
    ln_kernel<<<M_, 256>>>(px2, ln2w, ln2b, ph);
    tgemm_kernel<2><<<dim3(NFC/128, M_/128), 256>>>(ph, wfc, bfc,
                                                    nullptr, nullptr, pf,
                                                    M_, NFC, C_);
    tgemm_kernel<3><<<dim3(C_/128, M_/128), 256>>>(pf, wfc2, bfc2,
                                                   px2, nullptr, out_x,
                                                   M_, C_, NFC);
}

// round 3
// speedup vs baseline: 2.0738x; 1.0099x over previous
#include <cuda_runtime.h>
#include <math.h>
#include <stdint.h>

#define B_ 4
#define T_ 1024
#define C_ 1024
#define H_ 16
#define D_ 64
#define M_ (B_*T_)      /* 4096 rows */
#define NQKV 3072
#define NFC  4096

// ---------------- scratch (__device__ globals: no allocation allowed) -------
__device__ float g_h  [M_*C_];                 // LN output (reused for LN2)
__device__ float g_q  [M_*C_];                 // (B,H,T,D)
__device__ float g_k  [M_*C_];
__device__ float g_v  [M_*C_];
__device__ float g_y  [M_*C_];                 // attn output (B,T,C)
__device__ float g_x2 [M_*C_];                 // masked residual after proj
__device__ float g_f  [(size_t)M_*NFC];        // gelu(fc) activations (64MB)
__device__ float g_imp[M_];                    // importance (B,T)
__device__ float g_msk[M_];                    // combined mask

// ---------------- helpers ---------------------------------------------------
__device__ __forceinline__ float to_tf32(float x) {
    uint32_t u;
    asm("cvt.rna.tf32.f32 %0, %1;" : "=r"(u) : "f"(x));
    return __uint_as_float(u);
}

__device__ __forceinline__ void mma_tf32(float c[4], const float a[4], const float b[2]) {
    asm volatile(
        "mma.sync.aligned.m16n8k8.row.col.f32.tf32.tf32.f32 "
        "{%0,%1,%2,%3}, {%4,%5,%6,%7}, {%8,%9}, {%0,%1,%2,%3};"
        : "+f"(c[0]), "+f"(c[1]), "+f"(c[2]), "+f"(c[3])
        : "r"(__float_as_uint(a[0])), "r"(__float_as_uint(a[1])),
          "r"(__float_as_uint(a[2])), "r"(__float_as_uint(a[3])),
          "r"(__float_as_uint(b[0])), "r"(__float_as_uint(b[1])));
}

// ---------------- small kernels --------------------------------------------
__global__ void zero_kernel(float* p, int n) {
    int i = blockIdx.x * 256 + threadIdx.x;
    if (i < n) p[i] = 0.f;
}

__global__ void mask_kernel(const float* __restrict__ imp,
                            const float* __restrict__ am,
                            const float* __restrict__ thr,
                            float* __restrict__ gmask,
                            float* __restrict__ outmask,
                            float* __restrict__ outloss) {
    int i = blockIdx.x * 256 + threadIdx.x;
    if (i < M_) {
        float pm = (imp[i] >= thr[0]) ? 1.f : 0.f;
        float cm = am[i] * pm;
        gmask[i]   = cm;
        outmask[i] = cm;
    }
    if (i == 0) outloss[0] = 0.f;
}

// ---------------- layer norm (one block per row) ----------------------------
__global__ void __launch_bounds__(256) ln_kernel(const float* __restrict__ x,
                                                 const float* __restrict__ w,
                                                 const float* __restrict__ b,
                                                 float* __restrict__ out) {
    int row = blockIdx.x;
    int tid = threadIdx.x;
    __shared__ float buf[C_];
    __shared__ float red[8];
    const float* xr = x + (size_t)row * C_;
    float s = 0.f;
    #pragma unroll
    for (int j = tid; j < C_; j += 256) { float v = xr[j]; buf[j] = v; s += v; }
    #pragma unroll
    for (int o = 16; o; o >>= 1) s += __shfl_down_sync(~0u, s, o);
    if ((tid & 31) == 0) red[tid >> 5] = s;
    __syncthreads();
    if (tid < 8) {
        s = red[tid];
        #pragma unroll
        for (int o = 4; o; o >>= 1) s += __shfl_down_sync(0xff, s, o);
        if (tid == 0) red[0] = s;
    }
    __syncthreads();
    float mu = red[0] * (1.f / C_);
    __syncthreads();
    float ss = 0.f;
    #pragma unroll
    for (int j = tid; j < C_; j += 256) { float d = buf[j] - mu; ss += d * d; }
    #pragma unroll
    for (int o = 16; o; o >>= 1) ss += __shfl_down_sync(~0u, ss, o);
    if ((tid & 31) == 0) red[tid >> 5] = ss;
    __syncthreads();
    if (tid < 8) {
        ss = red[tid];
        #pragma unroll
        for (int o = 4; o; o >>= 1) ss += __shfl_down_sync(0xff, ss, o);
        if (tid == 0) red[0] = ss;
    }
    __syncthreads();
    float rstd = rsqrtf(red[0] * (1.f / C_) + 1e-5f);
    float* orow = out + (size_t)row * C_;
    #pragma unroll
    for (int j = tid; j < C_; j += 256)
        orow[j] = (buf[j] - mu) * rstd * w[j] + b[j];
}

// ---------------- tf32 tensor-core GEMM: 128x128x16, 8 warps (2x4) ---------
#define SPAD 136

template<int EPI>
__global__ void __launch_bounds__(256, 2) tgemm_kernel(
    const float* __restrict__ A, const float* __restrict__ W,
    const float* __restrict__ bias, const float* __restrict__ res,
    const float* __restrict__ mask, float* __restrict__ Cout,
    int M, int N, int K)
{
    __shared__ float As[2][16][SPAD];   // [k][m]
    __shared__ float Bs[2][16][SPAD];   // [k][n]
    int tid  = threadIdx.x;
    int lane = tid & 31;
    int wid  = tid >> 5;
    int warpM = wid >> 2, warpN = wid & 3;
    int g  = lane >> 2, tg = lane & 3;
    int row0 = blockIdx.y * 128, col0 = blockIdx.x * 128;

    int aRow0 = tid >> 2,         aK0 = (tid & 3) << 2;
    int aRow1 = (tid + 256) >> 2, aK1 = aK0;
    int bRow0 = tid >> 5,       bCol0 = (tid & 31) << 2;
    int bRow1 = bRow0 + 8,      bCol1 = bCol0;

    const float* aP0 = A + (size_t)(row0 + aRow0) * K + aK0;
    const float* aP1 = A + (size_t)(row0 + aRow1) * K + aK1;

    float acc[4][4][4] = {};
    int nk = K >> 4;

    {
        float4 va0 = *(const float4*)aP0;
        float4 va1 = *(const float4*)aP1;
        float4 vb0 = *(const float4*)(W + (size_t)bRow0 * N + col0 + bCol0);
        float4 vb1 = *(const float4*)(W + (size_t)bRow1 * N + col0 + bCol1);
        As[0][aK0+0][aRow0] = to_tf32(va0.x); As[0][aK0+1][aRow0] = to_tf32(va0.y);
        As[0][aK0+2][aRow0] = to_tf32(va0.z); As[0][aK0+3][aRow0] = to_tf32(va0.w);
        As[0][aK1+0][aRow1] = to_tf32(va1.x); As[0][aK1+1][aRow1] = to_tf32(va1.y);
        As[0][aK1+2][aRow1] = to_tf32(va1.z); As[0][aK1+3][aRow1] = to_tf32(va1.w);
        Bs[0][bRow0][bCol0+0] = to_tf32(vb0.x); Bs[0][bRow0][bCol0+1] = to_tf32(vb0.y);
        Bs[0][bRow0][bCol0+2] = to_tf32(vb0.z); Bs[0][bRow0][bCol0+3] = to_tf32(vb0.w);
        Bs[0][bRow1][bCol1+0] = to_tf32(vb1.x); Bs[0][bRow1][bCol1+1] = to_tf32(vb1.y);
        Bs[0][bRow1][bCol1+2] = to_tf32(vb1.z); Bs[0][bRow1][bCol1+3] = to_tf32(vb1.w);
    }
    __syncthreads();

    int mBase = warpM * 64;
    int nBase = warpN * 32;

    for (int kt = 0; kt < nk; kt++) {
        int cur = kt & 1;
        float4 va0, va1, vb0, vb1;
        if (kt + 1 < nk) {
            int k0 = (kt + 1) * 16;
            va0 = *(const float4*)(aP0 + k0);
            va1 = *(const float4*)(aP1 + k0);
            vb0 = *(const float4*)(W + (size_t)(k0 + bRow0) * N + col0 + bCol0);
            vb1 = *(const float4*)(W + (size_t)(k0 + bRow1) * N + col0 + bCol1);
        }
        #pragma unroll
        for (int kk = 0; kk < 16; kk += 8) {
            float a[4][4], b[4][2];
            #pragma unroll
            for (int mi = 0; mi < 4; mi++) {
                int m = mBase + mi * 16 + g;
                a[mi][0] = As[cur][kk + tg    ][m];
                a[mi][1] = As[cur][kk + tg    ][m + 8];
                a[mi][2] = As[cur][kk + tg + 4][m];
                a[mi][3] = As[cur][kk + tg + 4][m + 8];
            }
            #pragma unroll
            for (int ni = 0; ni < 4; ni++) {
                int n = nBase + ni * 8 + g;
                b[ni][0] = Bs[cur][kk + tg    ][n];
                b[ni][1] = Bs[cur][kk + tg + 4][n];
            }
            #pragma unroll
            for (int mi = 0; mi < 4; mi++)
                #pragma unroll
                for (int ni = 0; ni < 4; ni++)
                    mma_tf32(acc[mi][ni], a[mi], b[ni]);
        }
        if (kt + 1 < nk) {
            int nxt = 1 - cur;
            As[nxt][aK0+0][aRow0] = to_tf32(va0.x); As[nxt][aK0+1][aRow0] = to_tf32(va0.y);
            As[nxt][aK0+2][aRow0] = to_tf32(va0.z); As[nxt][aK0+3][aRow0] = to_tf32(va0.w);
            As[nxt][aK1+0][aRow1] = to_tf32(va1.x); As[nxt][aK1+1][aRow1] = to_tf32(va1.y);
            As[nxt][aK1+2][aRow1] = to_tf32(va1.z); As[nxt][aK1+3][aRow1] = to_tf32(va1.w);
            Bs[nxt][bRow0][bCol0+0] = to_tf32(vb0.x); Bs[nxt][bRow0][bCol0+1] = to_tf32(vb0.y);
            Bs[nxt][bRow0][bCol0+2] = to_tf32(vb0.z); Bs[nxt][bRow0][bCol0+3] = to_tf32(vb0.w);
            Bs[nxt][bRow1][bCol1+0] = to_tf32(vb1.x); Bs[nxt][bRow1][bCol1+1] = to_tf32(vb1.y);
            Bs[nxt][bRow1][bCol1+2] = to_tf32(vb1.z); Bs[nxt][bRow1][bCol1+3] = to_tf32(vb1.w);
            __syncthreads();
        }
    }

    #pragma unroll
    for (int mi = 0; mi < 4; mi++) {
        #pragma unroll
        for (int half = 0; half < 2; half++) {
            int ig = row0 + mBase + mi * 16 + g + half * 8;
            #pragma unroll
            for (int ni = 0; ni < 4; ni++) {
                float v0 = acc[mi][ni][2 * half + 0];
                float v1 = acc[mi][ni][2 * half + 1];
                int jg = col0 + nBase + ni * 8 + tg * 2;
                if (EPI == 0) {        // QKV scatter
                    int bq = ig >> 10, t = ig & 1023;
                    #pragma unroll
                    for (int e = 0; e < 2; e++) {
                        int j = jg + e;
                        int part = j >> 10;
                        int c = j & 1023;
                        int h = c >> 6, d = c & 63;
                        float val = (e ? v1 : v0) + bias[j];
                        float* dst = (part == 0) ? g_q : (part == 1) ? g_k : g_v;
                        dst[((size_t)(bq * H_ + h) * T_ + t) * D_ + d] = val;
                    }
                } else if (EPI == 1) { // proj: (x + y@W + b) * mask[row]
                    float mrow = mask[ig];
                    Cout[(size_t)ig * N + jg]     = (res[(size_t)ig * N + jg]     + v0 + bias[jg])     * mrow;
                    Cout[(size_t)ig * N + jg + 1] = (res[(size_t)ig * N + jg + 1] + v1 + bias[jg + 1]) * mrow;
                } else if (EPI == 2) { // exact GELU
                    float a0 = v0 + bias[jg], a1 = v1 + bias[jg + 1];
                    Cout[(size_t)ig * N + jg]     = 0.5f * a0 * (1.f + erff(a0 * 0.70710678118654752f));
                    Cout[(size_t)ig * N + jg + 1] = 0.5f * a1 * (1.f + erff(a1 * 0.70710678118654752f));
                } else {               // residual
                    Cout[(size_t)ig * N + jg]     = res[(size_t)ig * N + jg]     + v0 + bias[jg];
                    Cout[(size_t)ig * N + jg + 1] = res[(size_t)ig * N + jg + 1] + v1 + bias[jg + 1];
                }
            }
        }
    }
}

// ======================= FUSED FLASH ATTENTION ==============================
// One block = 32 query rows of one (b,h). Whole 32x1024 score strip lives in
// smem. tf32 tensor cores with 3-term hi/lo split (~fp32 accuracy).
// Phases: Q@K^T -> softmax(+causal,+key mask) -> colsum(importance) -> S@V.
#define QT 32
#define SSTR 1032            /* 1024 + 8 pad floats */
#define KSTR 68              /* 64 + 4 pad floats */

#define SM_S    0
#define SM_QHI  (QT*SSTR)                    /* 33024 */
#define SM_QLO  (SM_QHI + QT*KSTR)           /* +2176 */
#define SM_KHI  (SM_QLO + QT*KSTR)
#define SM_KLO  (SM_KHI + 64*KSTR)           /* +4352 */
#define SM_AM   (SM_KLO + 64*KSTR)
#define SM_TOTF (SM_AM + 1024)
#define FA_SMEM (SM_TOTF * 4)                /* 188416 bytes */

__global__ void __launch_bounds__(256, 1) fattn_kernel(
    const float* __restrict__ q, const float* __restrict__ k,
    const float* __restrict__ v, const float* __restrict__ am,
    float* __restrict__ y, float* __restrict__ imp)
{
    extern __shared__ float sm[];
    float* S   = sm + SM_S;
    float* Qhi = sm + SM_QHI;
    float* Qlo = sm + SM_QLO;
    float* Khi = sm + SM_KHI;
    float* Klo = sm + SM_KLO;
    float* amS = sm + SM_AM;

    int qt = gridDim.x - 1 - blockIdx.x;     // big tiles scheduled first
    int bh = blockIdx.y;
    int b  = bh >> 4, h = bh & 15;
    int tid  = threadIdx.x;
    int lane = tid & 31;
    int wid  = tid >> 5;
    int g = lane >> 2, tg = lane & 3;

    int q0   = qt * QT;
    int kend = q0 + QT;
    int nch  = (kend + 63) >> 6;

    const float* qb = q + (size_t)bh * T_ * D_;
    const float* kb = k + (size_t)bh * T_ * D_;
    const float* vb = v + (size_t)bh * T_ * D_;

    // ---- load Q tile (32x64) as hi/lo, and key mask ----
    {
        int row = tid >> 3, c0 = (tid & 7) * 8;
        const float* src = qb + (size_t)(q0 + row) * D_ + c0;
        #pragma unroll
        for (int e = 0; e < 8; e++) {
            float x = src[e];
            float hi = to_tf32(x);
            Qhi[row * KSTR + c0 + e] = hi;
            Qlo[row * KSTR + c0 + e] = to_tf32(x - hi);
        }
        for (int j = tid; j < T_; j += 256) amS[j] = am[b * T_ + j];
    }

    // ---- phase 1: S = (Q @ K^T) * 0.125 ----
    int mh = wid >> 2;          // 0/1: rows mh*16..+15
    int nq = wid & 3;           // col group of 16 within chunk
    for (int kc = 0; kc < nch; kc++) {
        __syncthreads();
        // load K chunk rows [kc*64, +64)
        for (int idx = tid; idx < 64 * 16; idx += 256) {
            int r = idx >> 4, c4 = (idx & 15) * 4;
            float4 val = *(const float4*)(kb + (size_t)(kc * 64 + r) * D_ + c4);
            float x, hi;
            x = val.x; hi = to_tf32(x); Khi[r*KSTR+c4+0] = hi; Klo[r*KSTR+c4+0] = to_tf32(x-hi);
            x = val.y; hi = to_tf32(x); Khi[r*KSTR+c4+1] = hi; Klo[r*KSTR+c4+1] = to_tf32(x-hi);
            x = val.z; hi = to_tf32(x); Khi[r*KSTR+c4+2] = hi; Klo[r*KSTR+c4+2] = to_tf32(x-hi);
            x = val.w; hi = to_tf32(x); Khi[r*KSTR+c4+3] = hi; Klo[r*KSTR+c4+3] = to_tf32(x-hi);
        }
        __syncthreads();

        float acc[2][4] = {};
        #pragma unroll
        for (int ks = 0; ks < 8; ks++) {
            int kk = ks * 8;
            float ah[4], al[4];
            int m0 = mh * 16;
            ah[0] = Qhi[(m0 + g    ) * KSTR + kk + tg    ];
            ah[1] = Qhi[(m0 + g + 8) * KSTR + kk + tg    ];
            ah[2] = Qhi[(m0 + g    ) * KSTR + kk + tg + 4];
            ah[3] = Qhi[(m0 + g + 8) * KSTR + kk + tg + 4];
            al[0] = Qlo[(m0 + g    ) * KSTR + kk + tg    ];
            al[1] = Qlo[(m0 + g + 8) * KSTR + kk + tg    ];
            al[2] = Qlo[(m0 + g    ) * KSTR + kk + tg + 4];
            al[3] = Qlo[(m0 + g + 8) * KSTR + kk + tg + 4];
            #pragma unroll
            for (int f = 0; f < 2; f++) {
                int n = nq * 16 + f * 8 + g;
                float bh2[2], bl2[2];
                bh2[0] = Khi[n * KSTR + kk + tg    ];
                bh2[1] = Khi[n * KSTR + kk + tg + 4];
                bl2[0] = Klo[n * KSTR + kk + tg    ];
                bl2[1] = Klo[n * KSTR + kk + tg + 4];
                mma_tf32(acc[f], ah, bh2);
                mma_tf32(acc[f], ah, bl2);
                mma_tf32(acc[f], al, bh2);
            }
        }
        // write S chunk
        #pragma unroll
        for (int f = 0; f < 2; f++) {
            int n0 = kc * 64 + nq * 16 + f * 8 + tg * 2;
            int r0 = mh * 16 + g;
            S[r0 * SSTR + n0]           = acc[f][0] * 0.125f;
            S[r0 * SSTR + n0 + 1]       = acc[f][1] * 0.125f;
            S[(r0 + 8) * SSTR + n0]     = acc[f][2] * 0.125f;
            S[(r0 + 8) * SSTR + n0 + 1] = acc[f][3] * 0.125f;
        }
    }
    __syncthreads();

    // ---- phase 2: per-row softmax (causal + key mask), normalized ----
    int jmax = nch * 64;
    for (int r4 = 0; r4 < 4; r4++) {
        int row = wid * 4 + r4;
        int qg  = q0 + row;
        float* srow = S + row * SSTR;
        float lm = -1e30f;
        for (int j = lane; j <= qg; j += 32)
            if (amS[j] != 0.f) lm = fmaxf(lm, srow[j]);
        #pragma unroll
        for (int o = 16; o; o >>= 1) lm = fmaxf(lm, __shfl_xor_sync(~0u, lm, o));
        float ls = 0.f;
        for (int j = lane; j < jmax; j += 32) {
            bool valid = (j <= qg) && (amS[j] != 0.f);
            float e = valid ? __expf(srow[j] - lm) : 0.f;
            srow[j] = e;
            ls += e;
        }
        #pragma unroll
        for (int o = 16; o; o >>= 1) ls += __shfl_xor_sync(~0u, ls, o);
        float inv = 1.f / ls;
        for (int j = lane; j < jmax; j += 32) srow[j] *= inv;
    }
    __syncthreads();

    // ---- phase 2b: column sums -> importance atomics ----
    for (int j = tid; j < kend; j += 256) {
        float cs = 0.f;
        #pragma unroll
        for (int r = 0; r < QT; r++) cs += S[r * SSTR + j];
        atomicAdd(&imp[b * T_ + j], cs * (1.f / (H_ * T_)));
    }

    // ---- phase 3: y = S @ V ----
    int warpM = wid >> 2;       // 0/1
    int warpN = wid & 3;        // 0..3: 16 cols each
    float acc[2][4] = {};
    for (int kc = 0; kc < nch; kc++) {
        __syncthreads();
        // load V chunk into K buffers (hi/lo)
        for (int idx = tid; idx < 64 * 16; idx += 256) {
            int r = idx >> 4, c4 = (idx & 15) * 4;
            float4 val = *(const float4*)(vb + (size_t)(kc * 64 + r) * D_ + c4);
            float x, hi;
            x = val.x; hi = to_tf32(x); Khi[r*KSTR+c4+0] = hi; Klo[r*KSTR+c4+0] = to_tf32(x-hi);
            x = val.y; hi = to_tf32(x); Khi[r*KSTR+c4+1] = hi; Klo[r*KSTR+c4+1] = to_tf32(x-hi);
            x = val.z; hi = to_tf32(x); Khi[r*KSTR+c4+2] = hi; Klo[r*KSTR+c4+2] = to_tf32(x-hi);
            x = val.w; hi = to_tf32(x); Khi[r*KSTR+c4+3] = hi; Klo[r*KSTR+c4+3] = to_tf32(x-hi);
        }
        __syncthreads();
        #pragma unroll
        for (int ks = 0; ks < 8; ks++) {
            int kk = kc * 64 + ks * 8;
            int m0 = warpM * 16;
            float ah[4], al[4], s0;
            s0 = S[(m0 + g    ) * SSTR + kk + tg    ]; ah[0] = to_tf32(s0); al[0] = to_tf32(s0 - ah[0]);
            s0 = S[(m0 + g + 8) * SSTR + kk + tg    ]; ah[1] = to_tf32(s0); al[1] = to_tf32(s0 - ah[1]);
            s0 = S[(m0 + g    ) * SSTR + kk + tg + 4]; ah[2] = to_tf32(s0); al[2] = to_tf32(s0 - ah[2]);
            s0 = S[(m0 + g + 8) * SSTR + kk + tg + 4]; ah[3] = to_tf32(s0); al[3] = to_tf32(s0 - ah[3]);
            #pragma unroll
            for (int f = 0; f < 2; f++) {
                int n = warpN * 16 + f * 8 + g;
                int kr = ks * 8;
                float bh2[2], bl2[2];
                bh2[0] = Khi[(kr + tg    ) * KSTR + n];
                bh2[1] = Khi[(kr + tg + 4) * KSTR + n];
                bl2[0] = Klo[(kr + tg    ) * KSTR + n];
                bl2[1] = Klo[(kr + tg + 4) * KSTR + n];
                mma_tf32(acc[f], ah, bh2);
                mma_tf32(acc[f], ah, bl2);
                mma_tf32(acc[f], al, bh2);
            }
        }
    }
    // write y: (B,T,C) at column h*64
    #pragma unroll
    for (int f = 0; f < 2; f++) {
        #pragma unroll
        for (int half = 0; half < 2; half++) {
            int t = q0 + warpM * 16 + g + half * 8;
            int d = h * 64 + warpN * 16 + f * 8 + tg * 2;
            float2 val = make_float2(acc[f][2 * half], acc[f][2 * half + 1]);
            *(float2*)&y[(size_t)(b * T_ + t) * C_ + d] = val;
        }
    }
}

// ---------------- launch ----------------------------------------------------
extern "C" void kernel_launch(void* const* d_in, const int* in_sizes, int n_in,
                              void* d_out, int out_size) {
    const float* x     = (const float*)d_in[0];
    const float* am    = (const float*)d_in[1];
    const float* ln1w  = (const float*)d_in[2];
    const float* ln1b  = (const float*)d_in[3];
    const float* wattn = (const float*)d_in[4];
    const float* battn = (const float*)d_in[5];
    const float* wproj = (const float*)d_in[6];
    const float* bproj = (const float*)d_in[7];
    const float* thr   = (const float*)d_in[8];
    const float* ln2w  = (const float*)d_in[9];
    const float* ln2b  = (const float*)d_in[10];
    const float* wfc   = (const float*)d_in[11];
    const float* bfc   = (const float*)d_in[12];
    const float* wfc2  = (const float*)d_in[13];
    const float* bfc2  = (const float*)d_in[14];

    float* out      = (float*)d_out;
    float* out_x    = out;                       // (B,T,C)
    float* out_mask = out + out_size - 1 - M_;   // (B,T)
    float* out_loss = out + out_size - 1;        // scalar

    float *ph, *pq, *pk, *pv, *py, *px2, *pf, *pimp, *pmsk;
    cudaGetSymbolAddress((void**)&ph,   g_h);
    cudaGetSymbolAddress((void**)&pq,   g_q);
    cudaGetSymbolAddress((void**)&pk,   g_k);
    cudaGetSymbolAddress((void**)&pv,   g_v);
    cudaGetSymbolAddress((void**)&py,   g_y);
    cudaGetSymbolAddress((void**)&px2,  g_x2);
    cudaGetSymbolAddress((void**)&pf,   g_f);
    cudaGetSymbolAddress((void**)&pimp, g_imp);
    cudaGetSymbolAddress((void**)&pmsk, g_msk);

    static int smem_set = 0;
    if (!smem_set) {
        cudaFuncSetAttribute(fattn_kernel,
                             cudaFuncAttributeMaxDynamicSharedMemorySize, FA_SMEM);
        smem_set = 1;
    }

    zero_kernel<<<16, 256>>>(pimp, M_);
    ln_kernel<<<M_, 256>>>(x, ln1w, ln1b, ph);
    tgemm_kernel<0><<<dim3(NQKV/128, M_/128), 256>>>(ph, wattn, battn,
                                                     nullptr, nullptr, nullptr,
                                                     M_, NQKV, C_);
    fattn_kernel<<<dim3(T_/QT, B_*H_), 256, FA_SMEM>>>(pq, pk, pv, am, py, pimp);
    mask_kernel<<<16, 256>>>(pimp, am, thr, pmsk, out_mask, out_loss);
    tgemm_kernel<1><<<dim3(C_/128, M_/128), 256>>>(py, wproj, bproj,
                                                   x, pmsk, px2,
                                                   M_, C_, C_);
    ln_kernel<<<M_, 256>>>(px2, ln2w, ln2b, ph);
    tgemm_kernel<2><<<dim3(NFC/128, M_/128), 256>>>(ph, wfc, bfc,
                                                    nullptr, nullptr, pf,
                                                    M_, NFC, C_);
    tgemm_kernel<3><<<dim3(C_/128, M_/128), 256>>>(pf, wfc2, bfc2,
                                                   px2, nullptr, out_x,
                                                   M_, C_, NFC);
}

// round 4
// speedup vs baseline: 2.6658x; 1.2855x over previous
#include <cuda_runtime.h>
#include <math.h>
#include <stdint.h>

#define B_ 4
#define T_ 1024
#define C_ 1024
#define H_ 16
#define D_ 64
#define M_ (B_*T_)      /* 4096 rows */
#define NQKV 3072
#define NFC  4096

// ---------------- scratch (__device__ globals: no allocation allowed) -------
__device__ float g_h  [M_*C_];                 // LN output (reused for LN2)
__device__ float g_q  [M_*C_];                 // (B,H,T,D)
__device__ float g_k  [M_*C_];
__device__ float g_v  [M_*C_];
__device__ float g_y  [M_*C_];                 // attn output (B,T,C)
__device__ float g_x2 [M_*C_];                 // masked residual after proj
__device__ float g_f  [(size_t)M_*NFC];        // gelu(fc) activations (64MB)
__device__ float g_imp[M_];                    // importance (B,T)
__device__ float g_msk[M_];                    // combined mask

// ---------------- helpers ---------------------------------------------------
__device__ __forceinline__ float to_tf32(float x) {
    uint32_t u;
    asm("cvt.rna.tf32.f32 %0, %1;" : "=r"(u) : "f"(x));
    return __uint_as_float(u);
}

__device__ __forceinline__ void mma_tf32(float c[4], const float a[4], const float b[2]) {
    asm volatile(
        "mma.sync.aligned.m16n8k8.row.col.f32.tf32.tf32.f32 "
        "{%0,%1,%2,%3}, {%4,%5,%6,%7}, {%8,%9}, {%0,%1,%2,%3};"
        : "+f"(c[0]), "+f"(c[1]), "+f"(c[2]), "+f"(c[3])
        : "r"(__float_as_uint(a[0])), "r"(__float_as_uint(a[1])),
          "r"(__float_as_uint(a[2])), "r"(__float_as_uint(a[3])),
          "r"(__float_as_uint(b[0])), "r"(__float_as_uint(b[1])));
}

// ---------------- small kernels --------------------------------------------
__global__ void zero_kernel(float* p, int n) {
    int i = blockIdx.x * 256 + threadIdx.x;
    if (i < n) p[i] = 0.f;
}

__global__ void mask_kernel(const float* __restrict__ imp,
                            const float* __restrict__ am,
                            const float* __restrict__ thr,
                            float* __restrict__ gmask,
                            float* __restrict__ outmask,
                            float* __restrict__ outloss) {
    int i = blockIdx.x * 256 + threadIdx.x;
    if (i < M_) {
        float pm = (imp[i] >= thr[0]) ? 1.f : 0.f;
        float cm = am[i] * pm;
        gmask[i]   = cm;
        outmask[i] = cm;
    }
    if (i == 0) outloss[0] = 0.f;
}

// ---------------- layer norm (one block per row) ----------------------------
__global__ void __launch_bounds__(256) ln_kernel(const float* __restrict__ x,
                                                 const float* __restrict__ w,
                                                 const float* __restrict__ b,
                                                 float* __restrict__ out) {
    int row = blockIdx.x;
    int tid = threadIdx.x;
    __shared__ float buf[C_];
    __shared__ float red[8];
    const float* xr = x + (size_t)row * C_;
    float s = 0.f;
    #pragma unroll
    for (int j = tid; j < C_; j += 256) { float v = xr[j]; buf[j] = v; s += v; }
    #pragma unroll
    for (int o = 16; o; o >>= 1) s += __shfl_down_sync(~0u, s, o);
    if ((tid & 31) == 0) red[tid >> 5] = s;
    __syncthreads();
    if (tid < 8) {
        s = red[tid];
        #pragma unroll
        for (int o = 4; o; o >>= 1) s += __shfl_down_sync(0xff, s, o);
        if (tid == 0) red[0] = s;
    }
    __syncthreads();
    float mu = red[0] * (1.f / C_);
    __syncthreads();
    float ss = 0.f;
    #pragma unroll
    for (int j = tid; j < C_; j += 256) { float d = buf[j] - mu; ss += d * d; }
    #pragma unroll
    for (int o = 16; o; o >>= 1) ss += __shfl_down_sync(~0u, ss, o);
    if ((tid & 31) == 0) red[tid >> 5] = ss;
    __syncthreads();
    if (tid < 8) {
        ss = red[tid];
        #pragma unroll
        for (int o = 4; o; o >>= 1) ss += __shfl_down_sync(0xff, ss, o);
        if (tid == 0) red[0] = ss;
    }
    __syncthreads();
    float rstd = rsqrtf(red[0] * (1.f / C_) + 1e-5f);
    float* orow = out + (size_t)row * C_;
    #pragma unroll
    for (int j = tid; j < C_; j += 256)
        orow[j] = (buf[j] - mu) * rstd * w[j] + b[j];
}

// ---------------- tf32 tensor-core GEMM: 128x128x16, 8 warps (2x4) ---------
#define SPAD 136

template<int EPI>
__global__ void __launch_bounds__(256, 2) tgemm_kernel(
    const float* __restrict__ A, const float* __restrict__ W,
    const float* __restrict__ bias, const float* __restrict__ res,
    const float* __restrict__ mask, float* __restrict__ Cout,
    int M, int N, int K)
{
    __shared__ float As[2][16][SPAD];   // [k][m]
    __shared__ float Bs[2][16][SPAD];   // [k][n]
    int tid  = threadIdx.x;
    int lane = tid & 31;
    int wid  = tid >> 5;
    int warpM = wid >> 2, warpN = wid & 3;
    int g  = lane >> 2, tg = lane & 3;
    int row0 = blockIdx.y * 128, col0 = blockIdx.x * 128;

    int aRow0 = tid >> 2,         aK0 = (tid & 3) << 2;
    int aRow1 = (tid + 256) >> 2, aK1 = aK0;
    int bRow0 = tid >> 5,       bCol0 = (tid & 31) << 2;
    int bRow1 = bRow0 + 8,      bCol1 = bCol0;

    const float* aP0 = A + (size_t)(row0 + aRow0) * K + aK0;
    const float* aP1 = A + (size_t)(row0 + aRow1) * K + aK1;

    float acc[4][4][4] = {};
    int nk = K >> 4;

    {
        float4 va0 = *(const float4*)aP0;
        float4 va1 = *(const float4*)aP1;
        float4 vb0 = *(const float4*)(W + (size_t)bRow0 * N + col0 + bCol0);
        float4 vb1 = *(const float4*)(W + (size_t)bRow1 * N + col0 + bCol1);
        As[0][aK0+0][aRow0] = to_tf32(va0.x); As[0][aK0+1][aRow0] = to_tf32(va0.y);
        As[0][aK0+2][aRow0] = to_tf32(va0.z); As[0][aK0+3][aRow0] = to_tf32(va0.w);
        As[0][aK1+0][aRow1] = to_tf32(va1.x); As[0][aK1+1][aRow1] = to_tf32(va1.y);
        As[0][aK1+2][aRow1] = to_tf32(va1.z); As[0][aK1+3][aRow1] = to_tf32(va1.w);
        Bs[0][bRow0][bCol0+0] = to_tf32(vb0.x); Bs[0][bRow0][bCol0+1] = to_tf32(vb0.y);
        Bs[0][bRow0][bCol0+2] = to_tf32(vb0.z); Bs[0][bRow0][bCol0+3] = to_tf32(vb0.w);
        Bs[0][bRow1][bCol1+0] = to_tf32(vb1.x); Bs[0][bRow1][bCol1+1] = to_tf32(vb1.y);
        Bs[0][bRow1][bCol1+2] = to_tf32(vb1.z); Bs[0][bRow1][bCol1+3] = to_tf32(vb1.w);
    }
    __syncthreads();

    int mBase = warpM * 64;
    int nBase = warpN * 32;

    for (int kt = 0; kt < nk; kt++) {
        int cur = kt & 1;
        float4 va0, va1, vb0, vb1;
        if (kt + 1 < nk) {
            int k0 = (kt + 1) * 16;
            va0 = *(const float4*)(aP0 + k0);
            va1 = *(const float4*)(aP1 + k0);
            vb0 = *(const float4*)(W + (size_t)(k0 + bRow0) * N + col0 + bCol0);
            vb1 = *(const float4*)(W + (size_t)(k0 + bRow1) * N + col0 + bCol1);
        }
        #pragma unroll
        for (int kk = 0; kk < 16; kk += 8) {
            float a[4][4], b[4][2];
            #pragma unroll
            for (int mi = 0; mi < 4; mi++) {
                int m = mBase + mi * 16 + g;
                a[mi][0] = As[cur][kk + tg    ][m];
                a[mi][1] = As[cur][kk + tg    ][m + 8];
                a[mi][2] = As[cur][kk + tg + 4][m];
                a[mi][3] = As[cur][kk + tg + 4][m + 8];
            }
            #pragma unroll
            for (int ni = 0; ni < 4; ni++) {
                int n = nBase + ni * 8 + g;
                b[ni][0] = Bs[cur][kk + tg    ][n];
                b[ni][1] = Bs[cur][kk + tg + 4][n];
            }
            #pragma unroll
            for (int mi = 0; mi < 4; mi++)
                #pragma unroll
                for (int ni = 0; ni < 4; ni++)
                    mma_tf32(acc[mi][ni], a[mi], b[ni]);
        }
        if (kt + 1 < nk) {
            int nxt = 1 - cur;
            As[nxt][aK0+0][aRow0] = to_tf32(va0.x); As[nxt][aK0+1][aRow0] = to_tf32(va0.y);
            As[nxt][aK0+2][aRow0] = to_tf32(va0.z); As[nxt][aK0+3][aRow0] = to_tf32(va0.w);
            As[nxt][aK1+0][aRow1] = to_tf32(va1.x); As[nxt][aK1+1][aRow1] = to_tf32(va1.y);
            As[nxt][aK1+2][aRow1] = to_tf32(va1.z); As[nxt][aK1+3][aRow1] = to_tf32(va1.w);
            Bs[nxt][bRow0][bCol0+0] = to_tf32(vb0.x); Bs[nxt][bRow0][bCol0+1] = to_tf32(vb0.y);
            Bs[nxt][bRow0][bCol0+2] = to_tf32(vb0.z); Bs[nxt][bRow0][bCol0+3] = to_tf32(vb0.w);
            Bs[nxt][bRow1][bCol1+0] = to_tf32(vb1.x); Bs[nxt][bRow1][bCol1+1] = to_tf32(vb1.y);
            Bs[nxt][bRow1][bCol1+2] = to_tf32(vb1.z); Bs[nxt][bRow1][bCol1+3] = to_tf32(vb1.w);
            __syncthreads();
        }
    }

    #pragma unroll
    for (int mi = 0; mi < 4; mi++) {
        #pragma unroll
        for (int half = 0; half < 2; half++) {
            int ig = row0 + mBase + mi * 16 + g + half * 8;
            #pragma unroll
            for (int ni = 0; ni < 4; ni++) {
                float v0 = acc[mi][ni][2 * half + 0];
                float v1 = acc[mi][ni][2 * half + 1];
                int jg = col0 + nBase + ni * 8 + tg * 2;
                if (EPI == 0) {        // QKV scatter
                    int bq = ig >> 10, t = ig & 1023;
                    #pragma unroll
                    for (int e = 0; e < 2; e++) {
                        int j = jg + e;
                        int part = j >> 10;
                        int c = j & 1023;
                        int h = c >> 6, d = c & 63;
                        float val = (e ? v1 : v0) + bias[j];
                        float* dst = (part == 0) ? g_q : (part == 1) ? g_k : g_v;
                        dst[((size_t)(bq * H_ + h) * T_ + t) * D_ + d] = val;
                    }
                } else if (EPI == 1) { // proj: (x + y@W + b) * mask[row]
                    float mrow = mask[ig];
                    Cout[(size_t)ig * N + jg]     = (res[(size_t)ig * N + jg]     + v0 + bias[jg])     * mrow;
                    Cout[(size_t)ig * N + jg + 1] = (res[(size_t)ig * N + jg + 1] + v1 + bias[jg + 1]) * mrow;
                } else if (EPI == 2) { // exact GELU
                    float a0 = v0 + bias[jg], a1 = v1 + bias[jg + 1];
                    Cout[(size_t)ig * N + jg]     = 0.5f * a0 * (1.f + erff(a0 * 0.70710678118654752f));
                    Cout[(size_t)ig * N + jg + 1] = 0.5f * a1 * (1.f + erff(a1 * 0.70710678118654752f));
                } else {               // residual
                    Cout[(size_t)ig * N + jg]     = res[(size_t)ig * N + jg]     + v0 + bias[jg];
                    Cout[(size_t)ig * N + jg + 1] = res[(size_t)ig * N + jg + 1] + v1 + bias[jg + 1];
                }
            }
        }
    }
}

// ======================= FUSED FLASH ATTENTION (v2) =========================
// One block = 32 query rows of one (b,h), 512 threads (16 warps).
// Single tf32 (no hi/lo split). Q fragments register-resident.
// smem: S strip fp32 (stride 1028), Q (stride 68), K/V chunk (stride 68/72).
#define QT 32
#define SSTR 1028            /* conflict-free fragment access */
#define KSTR 68              /* K rows [n][k] */
#define VSTR 72              /* V rows [key][d] */

#define SM_S    0
#define SM_Q    (QT*SSTR)                    /* 32896 */
#define SM_KV   (SM_Q + QT*KSTR)             /* +2176 */
#define SM_AM   (SM_KV + 128*VSTR)           /* +9216 */
#define SM_TOTF (SM_AM + 1024)
#define FA_SMEM (SM_TOTF * 4)                /* 181248 bytes */

__global__ void __launch_bounds__(512, 1) fattn_kernel(
    const float* __restrict__ q, const float* __restrict__ k,
    const float* __restrict__ v, const float* __restrict__ am,
    float* __restrict__ y, float* __restrict__ imp)
{
    extern __shared__ float sm[];
    float* S   = sm + SM_S;
    float* Qs  = sm + SM_Q;
    float* KVs = sm + SM_KV;
    float* amS = sm + SM_AM;

    int qt = gridDim.x - 1 - blockIdx.x;     // big tiles scheduled first
    int bh = blockIdx.y;
    int b  = bh >> 4, h = bh & 15;
    int tid  = threadIdx.x;
    int lane = tid & 31;
    int wid  = tid >> 5;                     // 0..15
    int g = lane >> 2, tg = lane & 3;

    int q0   = qt * QT;
    int kend = q0 + QT;
    int jmax = ((kend + 63) >> 6) << 6;      // multiple of 64

    const float* qb = q + (size_t)bh * T_ * D_;
    const float* kb = k + (size_t)bh * T_ * D_;
    const float* vb = v + (size_t)bh * T_ * D_;

    // ---- load Q tile (32x64, tf32-rounded) + key mask ----
    {
        int row = tid >> 4, c4 = (tid & 15) * 4;     // 512 float4 slots
        float4 val = *(const float4*)(qb + (size_t)(q0 + row) * D_ + c4);
        Qs[row * KSTR + c4 + 0] = to_tf32(val.x);
        Qs[row * KSTR + c4 + 1] = to_tf32(val.y);
        Qs[row * KSTR + c4 + 2] = to_tf32(val.z);
        Qs[row * KSTR + c4 + 3] = to_tf32(val.w);
        for (int j = tid; j < T_; j += 512) amS[j] = am[b * T_ + j];
    }
    __syncthreads();

    int warpRow = wid >> 3;        // 0/1 -> rows warpRow*16..+15
    int warpCol = wid & 7;         // 0..7
    int m0 = warpRow * 16;

    // ---- register-resident Q fragments: 8 k-steps x 4 regs ----
    float aq[8][4];
    #pragma unroll
    for (int ks = 0; ks < 8; ks++) {
        int kk = ks * 8;
        aq[ks][0] = Qs[(m0 + g    ) * KSTR + kk + tg    ];
        aq[ks][1] = Qs[(m0 + g + 8) * KSTR + kk + tg    ];
        aq[ks][2] = Qs[(m0 + g    ) * KSTR + kk + tg + 4];
        aq[ks][3] = Qs[(m0 + g + 8) * KSTR + kk + tg + 4];
    }

    // ---- phase 1: S = (Q @ K^T) * 0.125 (chunks of 128 keys) ----
    for (int kc0 = 0; kc0 < jmax; kc0 += 128) {
        int rows_here = min(128, jmax - kc0);
        __syncthreads();
        for (int idx = tid; idx < rows_here * 16; idx += 512) {
            int r = idx >> 4, c4 = (idx & 15) * 4;
            float4 val = *(const float4*)(kb + (size_t)(kc0 + r) * D_ + c4);
            KVs[r * KSTR + c4 + 0] = to_tf32(val.x);
            KVs[r * KSTR + c4 + 1] = to_tf32(val.y);
            KVs[r * KSTR + c4 + 2] = to_tf32(val.z);
            KVs[r * KSTR + c4 + 3] = to_tf32(val.w);
        }
        __syncthreads();
        if (warpCol * 16 < rows_here) {
            float acc[2][4] = {};
            #pragma unroll
            for (int ks = 0; ks < 8; ks++) {
                int kk = ks * 8;
                #pragma unroll
                for (int f = 0; f < 2; f++) {
                    int n = warpCol * 16 + f * 8 + g;
                    float bb[2];
                    bb[0] = KVs[n * KSTR + kk + tg    ];
                    bb[1] = KVs[n * KSTR + kk + tg + 4];
                    mma_tf32(acc[f], aq[ks], bb);
                }
            }
            #pragma unroll
            for (int f = 0; f < 2; f++) {
                int n0 = kc0 + warpCol * 16 + f * 8 + tg * 2;
                int r0 = m0 + g;
                S[r0 * SSTR + n0]           = acc[f][0] * 0.125f;
                S[r0 * SSTR + n0 + 1]       = acc[f][1] * 0.125f;
                S[(r0 + 8) * SSTR + n0]     = acc[f][2] * 0.125f;
                S[(r0 + 8) * SSTR + n0 + 1] = acc[f][3] * 0.125f;
            }
        }
    }
    __syncthreads();

    // ---- phase 2: per-row softmax (causal + key mask); tf32-round probs ----
    #pragma unroll
    for (int r2 = 0; r2 < 2; r2++) {
        int row = wid * 2 + r2;
        int qg  = q0 + row;
        float* srow = S + row * SSTR;
        float lm = -1e30f;
        for (int j = lane; j <= qg; j += 32)
            if (amS[j] != 0.f) lm = fmaxf(lm, srow[j]);
        #pragma unroll
        for (int o = 16; o; o >>= 1) lm = fmaxf(lm, __shfl_xor_sync(~0u, lm, o));
        float ls = 0.f;
        for (int j = lane; j < jmax; j += 32) {
            bool valid = (j <= qg) && (amS[j] != 0.f);
            float e = valid ? __expf(srow[j] - lm) : 0.f;
            srow[j] = e;
            ls += e;
        }
        #pragma unroll
        for (int o = 16; o; o >>= 1) ls += __shfl_xor_sync(~0u, ls, o);
        float inv = 1.f / ls;
        for (int j = lane; j < jmax; j += 32)
            srow[j] = to_tf32(srow[j] * inv);
    }
    __syncthreads();

    // ---- phase 2b: column sums -> importance atomics ----
    for (int j = tid; j < kend; j += 512) {
        float cs = 0.f;
        #pragma unroll
        for (int r = 0; r < QT; r++) cs += S[r * SSTR + j];
        atomicAdd(&imp[b * T_ + j], cs * (1.f / (H_ * T_)));
    }

    // ---- phase 3: y = S @ V (chunks of 128 keys) ----
    int col0 = warpCol * 8;                // 8 output cols per warp
    float acc[4] = {};
    for (int kc0 = 0; kc0 < jmax; kc0 += 128) {
        int rows_here = min(128, jmax - kc0);
        __syncthreads();
        for (int idx = tid; idx < rows_here * 16; idx += 512) {
            int r = idx >> 4, c4 = (idx & 15) * 4;
            float4 val = *(const float4*)(vb + (size_t)(kc0 + r) * D_ + c4);
            KVs[r * VSTR + c4 + 0] = to_tf32(val.x);
            KVs[r * VSTR + c4 + 1] = to_tf32(val.y);
            KVs[r * VSTR + c4 + 2] = to_tf32(val.z);
            KVs[r * VSTR + c4 + 3] = to_tf32(val.w);
        }
        __syncthreads();
        int ksteps = rows_here >> 3;
        for (int ks = 0; ks < ksteps; ks++) {
            int kk = ks * 8;
            int jc = kc0 + kk;
            float a[4], bb[2];
            a[0] = S[(m0 + g    ) * SSTR + jc + tg    ];
            a[1] = S[(m0 + g + 8) * SSTR + jc + tg    ];
            a[2] = S[(m0 + g    ) * SSTR + jc + tg + 4];
            a[3] = S[(m0 + g + 8) * SSTR + jc + tg + 4];
            bb[0] = KVs[(kk + tg    ) * VSTR + col0 + g];
            bb[1] = KVs[(kk + tg + 4) * VSTR + col0 + g];
            mma_tf32(acc, a, bb);
        }
    }
    // write y: (B,T,C) at column h*64
    #pragma unroll
    for (int half = 0; half < 2; half++) {
        int t = q0 + m0 + g + half * 8;
        int d = h * 64 + col0 + tg * 2;
        float2 val = make_float2(acc[2 * half], acc[2 * half + 1]);
        *(float2*)&y[(size_t)(b * T_ + t) * C_ + d] = val;
    }
}

// ---------------- launch ----------------------------------------------------
extern "C" void kernel_launch(void* const* d_in, const int* in_sizes, int n_in,
                              void* d_out, int out_size) {
    const float* x     = (const float*)d_in[0];
    const float* am    = (const float*)d_in[1];
    const float* ln1w  = (const float*)d_in[2];
    const float* ln1b  = (const float*)d_in[3];
    const float* wattn = (const float*)d_in[4];
    const float* battn = (const float*)d_in[5];
    const float* wproj = (const float*)d_in[6];
    const float* bproj = (const float*)d_in[7];
    const float* thr   = (const float*)d_in[8];
    const float* ln2w  = (const float*)d_in[9];
    const float* ln2b  = (const float*)d_in[10];
    const float* wfc   = (const float*)d_in[11];
    const float* bfc   = (const float*)d_in[12];
    const float* wfc2  = (const float*)d_in[13];
    const float* bfc2  = (const float*)d_in[14];

    float* out      = (float*)d_out;
    float* out_x    = out;                       // (B,T,C)
    float* out_mask = out + out_size - 1 - M_;   // (B,T)
    float* out_loss = out + out_size - 1;        // scalar

    float *ph, *pq, *pk, *pv, *py, *px2, *pf, *pimp, *pmsk;
    cudaGetSymbolAddress((void**)&ph,   g_h);
    cudaGetSymbolAddress((void**)&pq,   g_q);
    cudaGetSymbolAddress((void**)&pk,   g_k);
    cudaGetSymbolAddress((void**)&pv,   g_v);
    cudaGetSymbolAddress((void**)&py,   g_y);
    cudaGetSymbolAddress((void**)&px2,  g_x2);
    cudaGetSymbolAddress((void**)&pf,   g_f);
    cudaGetSymbolAddress((void**)&pimp, g_imp);
    cudaGetSymbolAddress((void**)&pmsk, g_msk);

    static int smem_set = 0;
    if (!smem_set) {
        cudaFuncSetAttribute(fattn_kernel,
                             cudaFuncAttributeMaxDynamicSharedMemorySize, FA_SMEM);
        smem_set = 1;
    }

    zero_kernel<<<16, 256>>>(pimp, M_);
    ln_kernel<<<M_, 256>>>(x, ln1w, ln1b, ph);
    tgemm_kernel<0><<<dim3(NQKV/128, M_/128), 256>>>(ph, wattn, battn,
                                                     nullptr, nullptr, nullptr,
                                                     M_, NQKV, C_);
    fattn_kernel<<<dim3(T_/QT, B_*H_), 512, FA_SMEM>>>(pq, pk, pv, am, py, pimp);
    mask_kernel<<<16, 256>>>(pimp, am, thr, pmsk, out_mask, out_loss);
    tgemm_kernel<1><<<dim3(C_/128, M_/128), 256>>>(py, wproj, bproj,
                                                   x, pmsk, px2,
                                                   M_, C_, C_);
    ln_kernel<<<M_, 256>>>(px2, ln2w, ln2b, ph);
    tgemm_kernel<2><<<dim3(NFC/128, M_/128), 256>>>(ph, wfc, bfc,
                                                    nullptr, nullptr, pf,
                                                    M_, NFC, C_);
    tgemm_kernel<3><<<dim3(C_/128, M_/128), 256>>>(pf, wfc2, bfc2,
                                                   px2, nullptr, out_x,
                                                   M_, C_, NFC);
}

// round 5
// speedup vs baseline: 2.8698x; 1.0765x over previous
#include <cuda_runtime.h>
#include <math.h>
#include <stdint.h>

#define B_ 4
#define T_ 1024
#define C_ 1024
#define H_ 16
#define D_ 64
#define M_ (B_*T_)      /* 4096 rows */
#define NQKV 3072
#define NFC  4096

// ---------------- scratch (__device__ globals: no allocation allowed) -------
__device__ float g_h  [M_*C_];                 // LN output (reused for LN2)
__device__ float g_q  [M_*C_];                 // (B,H,T,D)
__device__ float g_k  [M_*C_];
__device__ float g_v  [M_*C_];
__device__ float g_y  [M_*C_];                 // attn output (B,T,C)
__device__ float g_x2 [M_*C_];                 // masked residual after proj
__device__ float g_f  [(size_t)M_*NFC];        // gelu(fc) activations (64MB)
__device__ float g_imp[M_];                    // importance (B,T)
__device__ float g_msk[M_];                    // combined mask

// ---------------- helpers ---------------------------------------------------
__device__ __forceinline__ float to_tf32(float x) {
    uint32_t u;
    asm("cvt.rna.tf32.f32 %0, %1;" : "=r"(u) : "f"(x));
    return __uint_as_float(u);
}

__device__ __forceinline__ void mma_tf32(float c[4], const float a[4], const float b[2]) {
    asm volatile(
        "mma.sync.aligned.m16n8k8.row.col.f32.tf32.tf32.f32 "
        "{%0,%1,%2,%3}, {%4,%5,%6,%7}, {%8,%9}, {%0,%1,%2,%3};"
        : "+f"(c[0]), "+f"(c[1]), "+f"(c[2]), "+f"(c[3])
        : "r"(__float_as_uint(a[0])), "r"(__float_as_uint(a[1])),
          "r"(__float_as_uint(a[2])), "r"(__float_as_uint(a[3])),
          "r"(__float_as_uint(b[0])), "r"(__float_as_uint(b[1])));
}

__device__ __forceinline__ void cp_async16(float* dst_smem, const float* src_gmem) {
    uint32_t d = (uint32_t)__cvta_generic_to_shared(dst_smem);
    asm volatile("cp.async.cg.shared.global [%0], [%1], 16;" :: "r"(d), "l"(src_gmem));
}
__device__ __forceinline__ void cp_commit() {
    asm volatile("cp.async.commit_group;");
}
template<int N>
__device__ __forceinline__ void cp_wait() {
    asm volatile("cp.async.wait_group %0;" :: "n"(N));
}

// ---------------- small kernels --------------------------------------------
__global__ void zero_kernel(float* p, int n) {
    int i = blockIdx.x * 256 + threadIdx.x;
    if (i < n) p[i] = 0.f;
}

__global__ void mask_kernel(const float* __restrict__ imp,
                            const float* __restrict__ am,
                            const float* __restrict__ thr,
                            float* __restrict__ gmask,
                            float* __restrict__ outmask,
                            float* __restrict__ outloss) {
    int i = blockIdx.x * 256 + threadIdx.x;
    if (i < M_) {
        float pm = (imp[i] >= thr[0]) ? 1.f : 0.f;
        float cm = am[i] * pm;
        gmask[i]   = cm;
        outmask[i] = cm;
    }
    if (i == 0) outloss[0] = 0.f;
}

// ---------------- layer norm (one block per row) ----------------------------
__global__ void __launch_bounds__(256) ln_kernel(const float* __restrict__ x,
                                                 const float* __restrict__ w,
                                                 const float* __restrict__ b,
                                                 float* __restrict__ out) {
    int row = blockIdx.x;
    int tid = threadIdx.x;
    __shared__ float buf[C_];
    __shared__ float red[8];
    const float* xr = x + (size_t)row * C_;
    float s = 0.f;
    #pragma unroll
    for (int j = tid; j < C_; j += 256) { float v = xr[j]; buf[j] = v; s += v; }
    #pragma unroll
    for (int o = 16; o; o >>= 1) s += __shfl_down_sync(~0u, s, o);
    if ((tid & 31) == 0) red[tid >> 5] = s;
    __syncthreads();
    if (tid < 8) {
        s = red[tid];
        #pragma unroll
        for (int o = 4; o; o >>= 1) s += __shfl_down_sync(0xff, s, o);
        if (tid == 0) red[0] = s;
    }
    __syncthreads();
    float mu = red[0] * (1.f / C_);
    __syncthreads();
    float ss = 0.f;
    #pragma unroll
    for (int j = tid; j < C_; j += 256) { float d = buf[j] - mu; ss += d * d; }
    #pragma unroll
    for (int o = 16; o; o >>= 1) ss += __shfl_down_sync(~0u, ss, o);
    if ((tid & 31) == 0) red[tid >> 5] = ss;
    __syncthreads();
    if (tid < 8) {
        ss = red[tid];
        #pragma unroll
        for (int o = 4; o; o >>= 1) ss += __shfl_down_sync(0xff, ss, o);
        if (tid == 0) red[0] = ss;
    }
    __syncthreads();
    float rstd = rsqrtf(red[0] * (1.f / C_) + 1e-5f);
    float* orow = out + (size_t)row * C_;
    #pragma unroll
    for (int j = tid; j < C_; j += 256)
        orow[j] = (buf[j] - mu) * rstd * w[j] + b[j];
}

// ---------------- tf32 GEMM: 128x128x16, cp.async 4-stage pipeline ---------
// A smem: [stage][128 rows][20]  (k contiguous, pad->conflict-free frag loads)
// B smem: [stage][16 k][136]     (n contiguous)
#define STG  4
#define AKP  20
#define BNP  136
#define A_ST (128*AKP)           /* 2560 floats */
#define B_ST (16*BNP)            /* 2176 floats */
#define GEMM_SMEM ((STG*(A_ST+B_ST))*4)   /* 75776 bytes */

template<int EPI>
__global__ void __launch_bounds__(256, 2) tgemm_kernel(
    const float* __restrict__ A, const float* __restrict__ W,
    const float* __restrict__ bias, const float* __restrict__ res,
    const float* __restrict__ mask, float* __restrict__ Cout,
    int M, int N, int K)
{
    extern __shared__ float smf[];
    float* As = smf;                    // 4 stages A
    float* Bs = smf + STG * A_ST;       // 4 stages B

    int tid  = threadIdx.x;
    int lane = tid & 31;
    int wid  = tid >> 5;
    int warpM = wid >> 2, warpN = wid & 3;
    int g  = lane >> 2, tg = lane & 3;
    int row0 = blockIdx.y * 128, col0 = blockIdx.x * 128;

    // copy mapping: A = 512 x 16B segs (row, kq); B = 512 segs (krow, nq)
    int ar0 = tid >> 2,  ak0 = (tid & 3) << 2;
    int ar1 = ar0 + 64;
    int br0 = tid >> 5,  bn0 = (tid & 31) << 2;
    int br1 = br0 + 8;

    float acc[4][4][4] = {};
    int nk = K >> 4;

    // prologue: fill STG-1 stages
    #pragma unroll
    for (int p = 0; p < STG - 1; p++) {
        int st = p;
        float* Ad = As + st * A_ST;
        float* Bd = Bs + st * B_ST;
        const float* Ag = A + (size_t)row0 * K + p * 16;
        const float* Bg = W + (size_t)(p * 16) * N + col0;
        cp_async16(Ad + ar0 * AKP + ak0, Ag + (size_t)ar0 * K + ak0);
        cp_async16(Ad + ar1 * AKP + ak0, Ag + (size_t)ar1 * K + ak0);
        cp_async16(Bd + br0 * BNP + bn0, Bg + (size_t)br0 * N + bn0);
        cp_async16(Bd + br1 * BNP + bn0, Bg + (size_t)br1 * N + bn0);
        cp_commit();
    }

    int mBase = warpM * 64;
    int nBase = warpN * 32;

    for (int kt = 0; kt < nk; kt++) {
        cp_wait<STG - 2>();
        __syncthreads();
        // issue tile kt+STG-1 (overwrites the stage all warps finished last iter)
        if (kt + STG - 1 < nk) {
            int tk = kt + STG - 1;
            int st = tk & (STG - 1);
            float* Ad = As + st * A_ST;
            float* Bd = Bs + st * B_ST;
            const float* Ag = A + (size_t)row0 * K + tk * 16;
            const float* Bg = W + (size_t)(tk * 16) * N + col0;
            cp_async16(Ad + ar0 * AKP + ak0, Ag + (size_t)ar0 * K + ak0);
            cp_async16(Ad + ar1 * AKP + ak0, Ag + (size_t)ar1 * K + ak0);
            cp_async16(Bd + br0 * BNP + bn0, Bg + (size_t)br0 * N + bn0);
            cp_async16(Bd + br1 * BNP + bn0, Bg + (size_t)br1 * N + bn0);
        }
        cp_commit();   // always one group per iteration (empty at tail)

        int st = kt & (STG - 1);
        const float* Ast = As + st * A_ST;
        const float* Bst = Bs + st * B_ST;
        #pragma unroll
        for (int kk = 0; kk < 16; kk += 8) {
            float a[4][4], b[4][2];
            #pragma unroll
            for (int mi = 0; mi < 4; mi++) {
                int m = mBase + mi * 16 + g;
                a[mi][0] = to_tf32(Ast[(m    ) * AKP + kk + tg    ]);
                a[mi][1] = to_tf32(Ast[(m + 8) * AKP + kk + tg    ]);
                a[mi][2] = to_tf32(Ast[(m    ) * AKP + kk + tg + 4]);
                a[mi][3] = to_tf32(Ast[(m + 8) * AKP + kk + tg + 4]);
            }
            #pragma unroll
            for (int ni = 0; ni < 4; ni++) {
                int n = nBase + ni * 8 + g;
                b[ni][0] = to_tf32(Bst[(kk + tg    ) * BNP + n]);
                b[ni][1] = to_tf32(Bst[(kk + tg + 4) * BNP + n]);
            }
            #pragma unroll
            for (int mi = 0; mi < 4; mi++)
                #pragma unroll
                for (int ni = 0; ni < 4; ni++)
                    mma_tf32(acc[mi][ni], a[mi], b[ni]);
        }
    }

    // ---- epilogue ----
    #pragma unroll
    for (int mi = 0; mi < 4; mi++) {
        #pragma unroll
        for (int half = 0; half < 2; half++) {
            int ig = row0 + mBase + mi * 16 + g + half * 8;
            #pragma unroll
            for (int ni = 0; ni < 4; ni++) {
                float v0 = acc[mi][ni][2 * half + 0];
                float v1 = acc[mi][ni][2 * half + 1];
                int jg = col0 + nBase + ni * 8 + tg * 2;
                if (EPI == 0) {        // QKV scatter
                    int bq = ig >> 10, t = ig & 1023;
                    #pragma unroll
                    for (int e = 0; e < 2; e++) {
                        int j = jg + e;
                        int part = j >> 10;
                        int c = j & 1023;
                        int h = c >> 6, d = c & 63;
                        float val = (e ? v1 : v0) + bias[j];
                        float* dst = (part == 0) ? g_q : (part == 1) ? g_k : g_v;
                        dst[((size_t)(bq * H_ + h) * T_ + t) * D_ + d] = val;
                    }
                } else if (EPI == 1) { // proj: (x + y@W + b) * mask[row]
                    float mrow = mask[ig];
                    Cout[(size_t)ig * N + jg]     = (res[(size_t)ig * N + jg]     + v0 + bias[jg])     * mrow;
                    Cout[(size_t)ig * N + jg + 1] = (res[(size_t)ig * N + jg + 1] + v1 + bias[jg + 1]) * mrow;
                } else if (EPI == 2) { // exact GELU
                    float a0 = v0 + bias[jg], a1 = v1 + bias[jg + 1];
                    Cout[(size_t)ig * N + jg]     = 0.5f * a0 * (1.f + erff(a0 * 0.70710678118654752f));
                    Cout[(size_t)ig * N + jg + 1] = 0.5f * a1 * (1.f + erff(a1 * 0.70710678118654752f));
                } else {               // residual
                    Cout[(size_t)ig * N + jg]     = res[(size_t)ig * N + jg]     + v0 + bias[jg];
                    Cout[(size_t)ig * N + jg + 1] = res[(size_t)ig * N + jg + 1] + v1 + bias[jg + 1];
                }
            }
        }
    }
}

// ======================= FUSED FLASH ATTENTION (v2) =========================
#define QT 32
#define SSTR 1028
#define KSTR 68
#define VSTR 72

#define SM_S    0
#define SM_Q    (QT*SSTR)
#define SM_KV   (SM_Q + QT*KSTR)
#define SM_AM   (SM_KV + 128*VSTR)
#define SM_TOTF (SM_AM + 1024)
#define FA_SMEM (SM_TOTF * 4)

__global__ void __launch_bounds__(512, 1) fattn_kernel(
    const float* __restrict__ q, const float* __restrict__ k,
    const float* __restrict__ v, const float* __restrict__ am,
    float* __restrict__ y, float* __restrict__ imp)
{
    extern __shared__ float sm[];
    float* S   = sm + SM_S;
    float* Qs  = sm + SM_Q;
    float* KVs = sm + SM_KV;
    float* amS = sm + SM_AM;

    int qt = gridDim.x - 1 - blockIdx.x;
    int bh = blockIdx.y;
    int b  = bh >> 4, h = bh & 15;
    int tid  = threadIdx.x;
    int lane = tid & 31;
    int wid  = tid >> 5;
    int g = lane >> 2, tg = lane & 3;

    int q0   = qt * QT;
    int kend = q0 + QT;
    int jmax = ((kend + 63) >> 6) << 6;

    const float* qb = q + (size_t)bh * T_ * D_;
    const float* kb = k + (size_t)bh * T_ * D_;
    const float* vb = v + (size_t)bh * T_ * D_;

    {
        int row = tid >> 4, c4 = (tid & 15) * 4;
        float4 val = *(const float4*)(qb + (size_t)(q0 + row) * D_ + c4);
        Qs[row * KSTR + c4 + 0] = to_tf32(val.x);
        Qs[row * KSTR + c4 + 1] = to_tf32(val.y);
        Qs[row * KSTR + c4 + 2] = to_tf32(val.z);
        Qs[row * KSTR + c4 + 3] = to_tf32(val.w);
        for (int j = tid; j < T_; j += 512) amS[j] = am[b * T_ + j];
    }
    __syncthreads();

    int warpRow = wid >> 3;
    int warpCol = wid & 7;
    int m0 = warpRow * 16;

    float aq[8][4];
    #pragma unroll
    for (int ks = 0; ks < 8; ks++) {
        int kk = ks * 8;
        aq[ks][0] = Qs[(m0 + g    ) * KSTR + kk + tg    ];
        aq[ks][1] = Qs[(m0 + g + 8) * KSTR + kk + tg    ];
        aq[ks][2] = Qs[(m0 + g    ) * KSTR + kk + tg + 4];
        aq[ks][3] = Qs[(m0 + g + 8) * KSTR + kk + tg + 4];
    }

    for (int kc0 = 0; kc0 < jmax; kc0 += 128) {
        int rows_here = min(128, jmax - kc0);
        __syncthreads();
        for (int idx = tid; idx < rows_here * 16; idx += 512) {
            int r = idx >> 4, c4 = (idx & 15) * 4;
            float4 val = *(const float4*)(kb + (size_t)(kc0 + r) * D_ + c4);
            KVs[r * KSTR + c4 + 0] = to_tf32(val.x);
            KVs[r * KSTR + c4 + 1] = to_tf32(val.y);
            KVs[r * KSTR + c4 + 2] = to_tf32(val.z);
            KVs[r * KSTR + c4 + 3] = to_tf32(val.w);
        }
        __syncthreads();
        if (warpCol * 16 < rows_here) {
            float acc[2][4] = {};
            #pragma unroll
            for (int ks = 0; ks < 8; ks++) {
                int kk = ks * 8;
                #pragma unroll
                for (int f = 0; f < 2; f++) {
                    int n = warpCol * 16 + f * 8 + g;
                    float bb[2];
                    bb[0] = KVs[n * KSTR + kk + tg    ];
                    bb[1] = KVs[n * KSTR + kk + tg + 4];
                    mma_tf32(acc[f], aq[ks], bb);
                }
            }
            #pragma unroll
            for (int f = 0; f < 2; f++) {
                int n0 = kc0 + warpCol * 16 + f * 8 + tg * 2;
                int r0 = m0 + g;
                S[r0 * SSTR + n0]           = acc[f][0] * 0.125f;
                S[r0 * SSTR + n0 + 1]       = acc[f][1] * 0.125f;
                S[(r0 + 8) * SSTR + n0]     = acc[f][2] * 0.125f;
                S[(r0 + 8) * SSTR + n0 + 1] = acc[f][3] * 0.125f;
            }
        }
    }
    __syncthreads();

    #pragma unroll
    for (int r2 = 0; r2 < 2; r2++) {
        int row = wid * 2 + r2;
        int qg  = q0 + row;
        float* srow = S + row * SSTR;
        float lm = -1e30f;
        for (int j = lane; j <= qg; j += 32)
            if (amS[j] != 0.f) lm = fmaxf(lm, srow[j]);
        #pragma unroll
        for (int o = 16; o; o >>= 1) lm = fmaxf(lm, __shfl_xor_sync(~0u, lm, o));
        float ls = 0.f;
        for (int j = lane; j < jmax; j += 32) {
            bool valid = (j <= qg) && (amS[j] != 0.f);
            float e = valid ? __expf(srow[j] - lm) : 0.f;
            srow[j] = e;
            ls += e;
        }
        #pragma unroll
        for (int o = 16; o; o >>= 1) ls += __shfl_xor_sync(~0u, ls, o);
        float inv = 1.f / ls;
        for (int j = lane; j < jmax; j += 32)
            srow[j] = to_tf32(srow[j] * inv);
    }
    __syncthreads();

    for (int j = tid; j < kend; j += 512) {
        float cs = 0.f;
        #pragma unroll
        for (int r = 0; r < QT; r++) cs += S[r * SSTR + j];
        atomicAdd(&imp[b * T_ + j], cs * (1.f / (H_ * T_)));
    }

    int col0 = warpCol * 8;
    float acc[4] = {};
    for (int kc0 = 0; kc0 < jmax; kc0 += 128) {
        int rows_here = min(128, jmax - kc0);
        __syncthreads();
        for (int idx = tid; idx < rows_here * 16; idx += 512) {
            int r = idx >> 4, c4 = (idx & 15) * 4;
            float4 val = *(const float4*)(vb + (size_t)(kc0 + r) * D_ + c4);
            KVs[r * VSTR + c4 + 0] = to_tf32(val.x);
            KVs[r * VSTR + c4 + 1] = to_tf32(val.y);
            KVs[r * VSTR + c4 + 2] = to_tf32(val.z);
            KVs[r * VSTR + c4 + 3] = to_tf32(val.w);
        }
        __syncthreads();
        int ksteps = rows_here >> 3;
        for (int ks = 0; ks < ksteps; ks++) {
            int kk = ks * 8;
            int jc = kc0 + kk;
            float a[4], bb[2];
            a[0] = S[(m0 + g    ) * SSTR + jc + tg    ];
            a[1] = S[(m0 + g + 8) * SSTR + jc + tg    ];
            a[2] = S[(m0 + g    ) * SSTR + jc + tg + 4];
            a[3] = S[(m0 + g + 8) * SSTR + jc + tg + 4];
            bb[0] = KVs[(kk + tg    ) * VSTR + col0 + g];
            bb[1] = KVs[(kk + tg + 4) * VSTR + col0 + g];
            mma_tf32(acc, a, bb);
        }
    }
    #pragma unroll
    for (int half = 0; half < 2; half++) {
        int t = q0 + m0 + g + half * 8;
        int d = h * 64 + col0 + tg * 2;
        float2 val = make_float2(acc[2 * half], acc[2 * half + 1]);
        *(float2*)&y[(size_t)(b * T_ + t) * C_ + d] = val;
    }
}

// ---------------- launch ----------------------------------------------------
extern "C" void kernel_launch(void* const* d_in, const int* in_sizes, int n_in,
                              void* d_out, int out_size) {
    const float* x     = (const float*)d_in[0];
    const float* am    = (const float*)d_in[1];
    const float* ln1w  = (const float*)d_in[2];
    const float* ln1b  = (const float*)d_in[3];
    const float* wattn = (const float*)d_in[4];
    const float* battn = (const float*)d_in[5];
    const float* wproj = (const float*)d_in[6];
    const float* bproj = (const float*)d_in[7];
    const float* thr   = (const float*)d_in[8];
    const float* ln2w  = (const float*)d_in[9];
    const float* ln2b  = (const float*)d_in[10];
    const float* wfc   = (const float*)d_in[11];
    const float* bfc   = (const float*)d_in[12];
    const float* wfc2  = (const float*)d_in[13];
    const float* bfc2  = (const float*)d_in[14];

    float* out      = (float*)d_out;
    float* out_x    = out;                       // (B,T,C)
    float* out_mask = out + out_size - 1 - M_;   // (B,T)
    float* out_loss = out + out_size - 1;        // scalar

    float *ph, *pq, *pk, *pv, *py, *px2, *pf, *pimp, *pmsk;
    cudaGetSymbolAddress((void**)&ph,   g_h);
    cudaGetSymbolAddress((void**)&pq,   g_q);
    cudaGetSymbolAddress((void**)&pk,   g_k);
    cudaGetSymbolAddress((void**)&pv,   g_v);
    cudaGetSymbolAddress((void**)&py,   g_y);
    cudaGetSymbolAddress((void**)&px2,  g_x2);
    cudaGetSymbolAddress((void**)&pf,   g_f);
    cudaGetSymbolAddress((void**)&pimp, g_imp);
    cudaGetSymbolAddress((void**)&pmsk, g_msk);

    static int smem_set = 0;
    if (!smem_set) {
        cudaFuncSetAttribute(fattn_kernel,
                             cudaFuncAttributeMaxDynamicSharedMemorySize, FA_SMEM);
        cudaFuncSetAttribute(tgemm_kernel<0>,
                             cudaFuncAttributeMaxDynamicSharedMemorySize, GEMM_SMEM);
        cudaFuncSetAttribute(tgemm_kernel<1>,
                             cudaFuncAttributeMaxDynamicSharedMemorySize, GEMM_SMEM);
        cudaFuncSetAttribute(tgemm_kernel<2>,
                             cudaFuncAttributeMaxDynamicSharedMemorySize, GEMM_SMEM);
        cudaFuncSetAttribute(tgemm_kernel<3>,
                             cudaFuncAttributeMaxDynamicSharedMemorySize, GEMM_SMEM);
        smem_set = 1;
    }

    zero_kernel<<<16, 256>>>(pimp, M_);
    ln_kernel<<<M_, 256>>>(x, ln1w, ln1b, ph);
    tgemm_kernel<0><<<dim3(NQKV/128, M_/128), 256, GEMM_SMEM>>>(ph, wattn, battn,
                                                     nullptr, nullptr, nullptr,
                                                     M_, NQKV, C_);
    fattn_kernel<<<dim3(T_/QT, B_*H_), 512, FA_SMEM>>>(pq, pk, pv, am, py, pimp);
    mask_kernel<<<16, 256>>>(pimp, am, thr, pmsk, out_mask, out_loss);
    tgemm_kernel<1><<<dim3(C_/128, M_/128), 256, GEMM_SMEM>>>(py, wproj, bproj,
                                                   x, pmsk, px2,
                                                   M_, C_, C_);
    ln_kernel<<<M_, 256>>>(px2, ln2w, ln2b, ph);
    tgemm_kernel<2><<<dim3(NFC/128, M_/128), 256, GEMM_SMEM>>>(ph, wfc, bfc,
                                                    nullptr, nullptr, pf,
                                                    M_, NFC, C_);
    tgemm_kernel<3><<<dim3(C_/128, M_/128), 256, GEMM_SMEM>>>(pf, wfc2, bfc2,
                                                   px2, nullptr, out_x,
                                                   M_, C_, NFC);
}

// round 7
// speedup vs baseline: 4.4487x; 1.5501x over previous
#include <cuda_runtime.h>
#include <cuda_fp16.h>
#include <math.h>
#include <stdint.h>

#define B_ 4
#define T_ 1024
#define C_ 1024
#define H_ 16
#define D_ 64
#define M_ (B_*T_)      /* 4096 rows */
#define NQKV 3072
#define NFC  4096

// ---------------- scratch (__device__ globals: no allocation allowed) -------
__device__ float g_q  [M_*C_];                 // (B,H,T,D) fp32 for attention
__device__ float g_k  [M_*C_];
__device__ float g_v  [M_*C_];
__device__ float g_x2 [M_*C_];                 // masked residual after proj
__device__ float g_imp[M_];
__device__ float g_msk[M_];
// fp16 operand buffers
__device__ __half g_h16[M_*C_];                      // LN out
__device__ __half g_y16[M_*C_];                      // attn out (B,T,C)
__device__ __half g_f16[(size_t)M_*NFC];             // gelu activations
__device__ __half g_wat[C_*NQKV];                    // weights transposed [N][K]
__device__ __half g_wpr[C_*C_];
__device__ __half g_wfc[(size_t)C_*NFC];
__device__ __half g_wf2[(size_t)NFC*C_];

// ---------------- helpers ---------------------------------------------------
__device__ __forceinline__ float to_tf32(float x) {
    uint32_t u;
    asm("cvt.rna.tf32.f32 %0, %1;" : "=r"(u) : "f"(x));
    return __uint_as_float(u);
}
__device__ __forceinline__ void mma_tf32(float c[4], const float a[4], const float b[2]) {
    asm volatile(
        "mma.sync.aligned.m16n8k8.row.col.f32.tf32.tf32.f32 "
        "{%0,%1,%2,%3}, {%4,%5,%6,%7}, {%8,%9}, {%0,%1,%2,%3};"
        : "+f"(c[0]), "+f"(c[1]), "+f"(c[2]), "+f"(c[3])
        : "r"(__float_as_uint(a[0])), "r"(__float_as_uint(a[1])),
          "r"(__float_as_uint(a[2])), "r"(__float_as_uint(a[3])),
          "r"(__float_as_uint(b[0])), "r"(__float_as_uint(b[1])));
}
__device__ __forceinline__ void mma_f16(float c[4], const uint32_t a[4], const uint32_t b[2]) {
    asm volatile(
        "mma.sync.aligned.m16n8k16.row.col.f32.f16.f16.f32 "
        "{%0,%1,%2,%3}, {%4,%5,%6,%7}, {%8,%9}, {%0,%1,%2,%3};"
        : "+f"(c[0]), "+f"(c[1]), "+f"(c[2]), "+f"(c[3])
        : "r"(a[0]), "r"(a[1]), "r"(a[2]), "r"(a[3]), "r"(b[0]), "r"(b[1]));
}
__device__ __forceinline__ void cp16(void* dst_smem, const void* src) {
    uint32_t d = (uint32_t)__cvta_generic_to_shared(dst_smem);
    asm volatile("cp.async.cg.shared.global [%0], [%1], 16;" :: "r"(d), "l"(src));
}
__device__ __forceinline__ void cp_commit() { asm volatile("cp.async.commit_group;"); }
template<int N_>
__device__ __forceinline__ void cp_wait() { asm volatile("cp.async.wait_group %0;" :: "n"(N_)); }

// ---------------- small kernels --------------------------------------------
__global__ void zero_kernel(float* p, int n) {
    int i = blockIdx.x * 256 + threadIdx.x;
    if (i < n) p[i] = 0.f;
}

__global__ void mask_kernel(const float* __restrict__ imp,
                            const float* __restrict__ am,
                            const float* __restrict__ thr,
                            float* __restrict__ gmask,
                            float* __restrict__ outmask,
                            float* __restrict__ outloss) {
    int i = blockIdx.x * 256 + threadIdx.x;
    if (i < M_) {
        float pm = (imp[i] >= thr[0]) ? 1.f : 0.f;
        float cm = am[i] * pm;
        gmask[i]   = cm;
        outmask[i] = cm;
    }
    if (i == 0) outloss[0] = 0.f;
}

// ---------------- weight transpose -> fp16 [N][K] ---------------------------
__global__ void __launch_bounds__(256) wsplit_kernel(const float* __restrict__ W,
                                                     __half* __restrict__ Oh,
                                                     int K, int N) {
    __shared__ float tile[32][33];
    int n0 = blockIdx.x * 32, k0 = blockIdx.y * 32;
    int tx = threadIdx.x & 31, ty = threadIdx.x >> 5;   // 32 x 8
    #pragma unroll
    for (int i = 0; i < 4; i++)
        tile[ty + i * 8][tx] = W[(size_t)(k0 + ty + i * 8) * N + n0 + tx];
    __syncthreads();
    #pragma unroll
    for (int i = 0; i < 4; i++) {
        int n = n0 + ty + i * 8;
        Oh[(size_t)n * K + k0 + tx] = __float2half_rn(tile[tx][ty + i * 8]);
    }
}

// ---------------- layer norm -> fp16 ----------------------------------------
__global__ void __launch_bounds__(256) ln_kernel(const float* __restrict__ x,
                                                 const float* __restrict__ w,
                                                 const float* __restrict__ b,
                                                 __half* __restrict__ oh) {
    int row = blockIdx.x;
    int tid = threadIdx.x;
    __shared__ float buf[C_];
    __shared__ float red[8];
    const float* xr = x + (size_t)row * C_;
    float s = 0.f;
    #pragma unroll
    for (int j = tid; j < C_; j += 256) { float v = xr[j]; buf[j] = v; s += v; }
    #pragma unroll
    for (int o = 16; o; o >>= 1) s += __shfl_down_sync(~0u, s, o);
    if ((tid & 31) == 0) red[tid >> 5] = s;
    __syncthreads();
    if (tid < 8) {
        s = red[tid];
        #pragma unroll
        for (int o = 4; o; o >>= 1) s += __shfl_down_sync(0xff, s, o);
        if (tid == 0) red[0] = s;
    }
    __syncthreads();
    float mu = red[0] * (1.f / C_);
    __syncthreads();
    float ss = 0.f;
    #pragma unroll
    for (int j = tid; j < C_; j += 256) { float d = buf[j] - mu; ss += d * d; }
    #pragma unroll
    for (int o = 16; o; o >>= 1) ss += __shfl_down_sync(~0u, ss, o);
    if ((tid & 31) == 0) red[tid >> 5] = ss;
    __syncthreads();
    if (tid < 8) {
        ss = red[tid];
        #pragma unroll
        for (int o = 4; o; o >>= 1) ss += __shfl_down_sync(0xff, ss, o);
        if (tid == 0) red[0] = ss;
    }
    __syncthreads();
    float rstd = rsqrtf(red[0] * (1.f / C_) + 1e-5f);
    #pragma unroll
    for (int j = tid; j < C_; j += 256)
        oh[(size_t)row * C_ + j] = __float2half_rn((buf[j] - mu) * rstd * w[j] + b[j]);
}

// ---------------- fp16 GEMM: 128x128x32-per-stage, cp.async 4-stage ---------
// A: fp16 [M][K] row-major; B: fp16 [N][K] row-major (pre-transposed weights).
// smem per stage: A 128 rows x 40 halves (32 data + 8 pad), B same.
#define STG  4
#define RSTR 40                          /* halves per row (20 u32) */
#define HALF_ST (128*RSTR)               /* 5120 halves = 10240 B per operand */
#define STAGE_U32 (2*HALF_ST/2)          /* A+B in u32 units: 5120 */
#define GEMM_SMEM (STG*2*HALF_ST*2)      /* 81920 bytes */

template<int EPI>
__global__ void __launch_bounds__(256, 2) tgemm_kernel(
    const __half* __restrict__ A, const __half* __restrict__ W,
    const float* __restrict__ bias, const float* __restrict__ res,
    const float* __restrict__ mask, float* __restrict__ Cout,
    int M, int N, int K)
{
    extern __shared__ uint32_t smu[];    // staged as u32
    // stage s: A at smu + s*STAGE_U32*2? -- lay out: per stage: A (2560 u32) then B (2560 u32)
    int tid  = threadIdx.x;
    int lane = tid & 31;
    int wid  = tid >> 5;
    int warpM = wid >> 2, warpN = wid & 3;
    int g  = lane >> 2, tg = lane & 3;
    int row0 = blockIdx.y * 128, col0 = blockIdx.x * 128;

    // copy mapping: 512 segs of 16B per operand; thread handles segs tid, tid+256
    // seg s: r = s>>2 (row), c = s&3 (16B chunk = 8 halves)
    int r0s = tid >> 2, c0s = tid & 3;
    int r1s = r0s + 64;

    float acc[4][4][4] = {};
    int nk = K >> 5;                     // stages of K=32

    auto load_stage = [&](int s, int buf) {
        uint32_t* Ad = smu + buf * 2 * 2560;
        uint32_t* Bd = Ad + 2560;
        size_t kb = (size_t)s * 32;
        const __half* Ag = A + (size_t)row0 * K + kb;
        const __half* Bg = W + (size_t)col0 * K + kb;
        cp16(Ad + r0s * 20 + c0s * 4, Ag + (size_t)r0s * K + c0s * 8);
        cp16(Ad + r1s * 20 + c0s * 4, Ag + (size_t)r1s * K + c0s * 8);
        cp16(Bd + r0s * 20 + c0s * 4, Bg + (size_t)r0s * K + c0s * 8);
        cp16(Bd + r1s * 20 + c0s * 4, Bg + (size_t)r1s * K + c0s * 8);
    };

    #pragma unroll
    for (int p = 0; p < STG - 1; p++) { load_stage(p, p); cp_commit(); }

    int mBase = warpM * 64;
    int nBase = warpN * 32;

    for (int kt = 0; kt < nk; kt++) {
        cp_wait<STG - 2>();
        __syncthreads();
        if (kt + STG - 1 < nk) load_stage(kt + STG - 1, (kt + STG - 1) & (STG - 1));
        cp_commit();

        int st = kt & (STG - 1);
        const uint32_t* Ast = smu + st * 2 * 2560;
        const uint32_t* Bst = Ast + 2560;
        #pragma unroll
        for (int kk2 = 0; kk2 < 2; kk2++) {          // two k-steps of 16
            int ko = kk2 * 8;                        // u32 offset within row
            uint32_t a[4][4], b[4][2];
            #pragma unroll
            for (int mi = 0; mi < 4; mi++) {
                int m = mBase + mi * 16 + g;
                a[mi][0] = Ast[(m    ) * 20 + ko + tg    ];
                a[mi][1] = Ast[(m + 8) * 20 + ko + tg    ];
                a[mi][2] = Ast[(m    ) * 20 + ko + tg + 4];
                a[mi][3] = Ast[(m + 8) * 20 + ko + tg + 4];
            }
            #pragma unroll
            for (int ni = 0; ni < 4; ni++) {
                int n = nBase + ni * 8 + g;
                b[ni][0] = Bst[n * 20 + ko + tg    ];
                b[ni][1] = Bst[n * 20 + ko + tg + 4];
            }
            #pragma unroll
            for (int mi = 0; mi < 4; mi++)
                #pragma unroll
                for (int ni = 0; ni < 4; ni++)
                    mma_f16(acc[mi][ni], a[mi], b[ni]);
        }
    }

    // ---- epilogue (same accumulator layout as tf32 m16n8k8) ----
    #pragma unroll
    for (int mi = 0; mi < 4; mi++) {
        #pragma unroll
        for (int half = 0; half < 2; half++) {
            int ig = row0 + mBase + mi * 16 + g + half * 8;
            #pragma unroll
            for (int ni = 0; ni < 4; ni++) {
                float v0 = acc[mi][ni][2 * half + 0];
                float v1 = acc[mi][ni][2 * half + 1];
                int jg = col0 + nBase + ni * 8 + tg * 2;
                if (EPI == 0) {        // QKV scatter
                    int bq = ig >> 10, t = ig & 1023;
                    #pragma unroll
                    for (int e = 0; e < 2; e++) {
                        int j = jg + e;
                        int part = j >> 10;
                        int c = j & 1023;
                        int h = c >> 6, d = c & 63;
                        float val = (e ? v1 : v0) + bias[j];
                        float* dst = (part == 0) ? g_q : (part == 1) ? g_k : g_v;
                        dst[((size_t)(bq * H_ + h) * T_ + t) * D_ + d] = val;
                    }
                } else if (EPI == 1) { // proj: (x + y@W + b) * mask[row]
                    float mrow = mask[ig];
                    Cout[(size_t)ig * N + jg]     = (res[(size_t)ig * N + jg]     + v0 + bias[jg])     * mrow;
                    Cout[(size_t)ig * N + jg + 1] = (res[(size_t)ig * N + jg + 1] + v1 + bias[jg + 1]) * mrow;
                } else if (EPI == 2) { // exact GELU -> fp16 activations
                    float a0 = v0 + bias[jg], a1 = v1 + bias[jg + 1];
                    float g0 = 0.5f * a0 * (1.f + erff(a0 * 0.70710678118654752f));
                    float g1 = 0.5f * a1 * (1.f + erff(a1 * 0.70710678118654752f));
                    __half2 hv; hv.x = __float2half_rn(g0); hv.y = __float2half_rn(g1);
                    *(__half2*)&g_f16[(size_t)ig * N + jg] = hv;
                } else {               // residual
                    Cout[(size_t)ig * N + jg]     = res[(size_t)ig * N + jg]     + v0 + bias[jg];
                    Cout[(size_t)ig * N + jg + 1] = res[(size_t)ig * N + jg + 1] + v1 + bias[jg + 1];
                }
            }
        }
    }
}

// ======================= FUSED FLASH ATTENTION (v2) =========================
#define QT 32
#define SSTR 1028
#define KSTR 68
#define VSTR 72
#define SM_S    0
#define SM_Q    (QT*SSTR)
#define SM_KV   (SM_Q + QT*KSTR)
#define SM_AM   (SM_KV + 128*VSTR)
#define SM_TOTF (SM_AM + 1024)
#define FA_SMEM (SM_TOTF * 4)

__global__ void __launch_bounds__(512, 1) fattn_kernel(
    const float* __restrict__ q, const float* __restrict__ k,
    const float* __restrict__ v, const float* __restrict__ am,
    __half* __restrict__ y16, float* __restrict__ imp)
{
    extern __shared__ float sm[];
    float* S   = sm + SM_S;
    float* Qs  = sm + SM_Q;
    float* KVs = sm + SM_KV;
    float* amS = sm + SM_AM;

    int qt = gridDim.x - 1 - blockIdx.x;
    int bh = blockIdx.y;
    int b  = bh >> 4, h = bh & 15;
    int tid  = threadIdx.x;
    int lane = tid & 31;
    int wid  = tid >> 5;
    int g = lane >> 2, tg = lane & 3;

    int q0   = qt * QT;
    int kend = q0 + QT;
    int jmax = ((kend + 63) >> 6) << 6;

    const float* qb = q + (size_t)bh * T_ * D_;
    const float* kb = k + (size_t)bh * T_ * D_;
    const float* vb = v + (size_t)bh * T_ * D_;

    {
        int row = tid >> 4, c4 = (tid & 15) * 4;
        float4 val = *(const float4*)(qb + (size_t)(q0 + row) * D_ + c4);
        Qs[row * KSTR + c4 + 0] = to_tf32(val.x);
        Qs[row * KSTR + c4 + 1] = to_tf32(val.y);
        Qs[row * KSTR + c4 + 2] = to_tf32(val.z);
        Qs[row * KSTR + c4 + 3] = to_tf32(val.w);
        for (int j = tid; j < T_; j += 512) amS[j] = am[b * T_ + j];
    }
    __syncthreads();

    int warpRow = wid >> 3;
    int warpCol = wid & 7;
    int m0 = warpRow * 16;

    float aq[8][4];
    #pragma unroll
    for (int ks = 0; ks < 8; ks++) {
        int kk = ks * 8;
        aq[ks][0] = Qs[(m0 + g    ) * KSTR + kk + tg    ];
        aq[ks][1] = Qs[(m0 + g + 8) * KSTR + kk + tg    ];
        aq[ks][2] = Qs[(m0 + g    ) * KSTR + kk + tg + 4];
        aq[ks][3] = Qs[(m0 + g + 8) * KSTR + kk + tg + 4];
    }

    for (int kc0 = 0; kc0 < jmax; kc0 += 128) {
        int rows_here = min(128, jmax - kc0);
        __syncthreads();
        for (int idx = tid; idx < rows_here * 16; idx += 512) {
            int r = idx >> 4, c4 = (idx & 15) * 4;
            float4 val = *(const float4*)(kb + (size_t)(kc0 + r) * D_ + c4);
            KVs[r * KSTR + c4 + 0] = to_tf32(val.x);
            KVs[r * KSTR + c4 + 1] = to_tf32(val.y);
            KVs[r * KSTR + c4 + 2] = to_tf32(val.z);
            KVs[r * KSTR + c4 + 3] = to_tf32(val.w);
        }
        __syncthreads();
        if (warpCol * 16 < rows_here) {
            float acc[2][4] = {};
            #pragma unroll
            for (int ks = 0; ks < 8; ks++) {
                int kk = ks * 8;
                #pragma unroll
                for (int f = 0; f < 2; f++) {
                    int n = warpCol * 16 + f * 8 + g;
                    float bb[2];
                    bb[0] = KVs[n * KSTR + kk + tg    ];
                    bb[1] = KVs[n * KSTR + kk + tg + 4];
                    mma_tf32(acc[f], aq[ks], bb);
                }
            }
            #pragma unroll
            for (int f = 0; f < 2; f++) {
                int n0 = kc0 + warpCol * 16 + f * 8 + tg * 2;
                int r0 = m0 + g;
                S[r0 * SSTR + n0]           = acc[f][0] * 0.125f;
                S[r0 * SSTR + n0 + 1]       = acc[f][1] * 0.125f;
                S[(r0 + 8) * SSTR + n0]     = acc[f][2] * 0.125f;
                S[(r0 + 8) * SSTR + n0 + 1] = acc[f][3] * 0.125f;
            }
        }
    }
    __syncthreads();

    #pragma unroll
    for (int r2 = 0; r2 < 2; r2++) {
        int row = wid * 2 + r2;
        int qg  = q0 + row;
        float* srow = S + row * SSTR;
        float lm = -1e30f;
        for (int j = lane; j <= qg; j += 32)
            if (amS[j] != 0.f) lm = fmaxf(lm, srow[j]);
        #pragma unroll
        for (int o = 16; o; o >>= 1) lm = fmaxf(lm, __shfl_xor_sync(~0u, lm, o));
        float ls = 0.f;
        for (int j = lane; j < jmax; j += 32) {
            bool valid = (j <= qg) && (amS[j] != 0.f);
            float e = valid ? __expf(srow[j] - lm) : 0.f;
            srow[j] = e;
            ls += e;
        }
        #pragma unroll
        for (int o = 16; o; o >>= 1) ls += __shfl_xor_sync(~0u, ls, o);
        float inv = 1.f / ls;
        for (int j = lane; j < jmax; j += 32)
            srow[j] = to_tf32(srow[j] * inv);
    }
    __syncthreads();

    for (int j = tid; j < kend; j += 512) {
        float cs = 0.f;
        #pragma unroll
        for (int r = 0; r < QT; r++) cs += S[r * SSTR + j];
        atomicAdd(&imp[b * T_ + j], cs * (1.f / (H_ * T_)));
    }

    int col0 = warpCol * 8;
    float acc[4] = {};
    for (int kc0 = 0; kc0 < jmax; kc0 += 128) {
        int rows_here = min(128, jmax - kc0);
        __syncthreads();
        for (int idx = tid; idx < rows_here * 16; idx += 512) {
            int r = idx >> 4, c4 = (idx & 15) * 4;
            float4 val = *(const float4*)(vb + (size_t)(kc0 + r) * D_ + c4);
            KVs[r * VSTR + c4 + 0] = to_tf32(val.x);
            KVs[r * VSTR + c4 + 1] = to_tf32(val.y);
            KVs[r * VSTR + c4 + 2] = to_tf32(val.z);
            KVs[r * VSTR + c4 + 3] = to_tf32(val.w);
        }
        __syncthreads();
        int ksteps = rows_here >> 3;
        for (int ks = 0; ks < ksteps; ks++) {
            int kk = ks * 8;
            int jc = kc0 + kk;
            float a[4], bb[2];
            a[0] = S[(m0 + g    ) * SSTR + jc + tg    ];
            a[1] = S[(m0 + g + 8) * SSTR + jc + tg    ];
            a[2] = S[(m0 + g    ) * SSTR + jc + tg + 4];
            a[3] = S[(m0 + g + 8) * SSTR + jc + tg + 4];
            bb[0] = KVs[(kk + tg    ) * VSTR + col0 + g];
            bb[1] = KVs[(kk + tg + 4) * VSTR + col0 + g];
            mma_tf32(acc, a, bb);
        }
    }
    #pragma unroll
    for (int half = 0; half < 2; half++) {
        int t = q0 + m0 + g + half * 8;
        int d = h * 64 + col0 + tg * 2;
        __half2 hv;
        hv.x = __float2half_rn(acc[2 * half]);
        hv.y = __float2half_rn(acc[2 * half + 1]);
        *(__half2*)&y16[(size_t)(b * T_ + t) * C_ + d] = hv;
    }
}

// ---------------- launch ----------------------------------------------------
extern "C" void kernel_launch(void* const* d_in, const int* in_sizes, int n_in,
                              void* d_out, int out_size) {
    const float* x     = (const float*)d_in[0];
    const float* am    = (const float*)d_in[1];
    const float* ln1w  = (const float*)d_in[2];
    const float* ln1b  = (const float*)d_in[3];
    const float* wattn = (const float*)d_in[4];
    const float* battn = (const float*)d_in[5];
    const float* wproj = (const float*)d_in[6];
    const float* bproj = (const float*)d_in[7];
    const float* thr   = (const float*)d_in[8];
    const float* ln2w  = (const float*)d_in[9];
    const float* ln2b  = (const float*)d_in[10];
    const float* wfc   = (const float*)d_in[11];
    const float* bfc   = (const float*)d_in[12];
    const float* wfc2  = (const float*)d_in[13];
    const float* bfc2  = (const float*)d_in[14];

    float* out      = (float*)d_out;
    float* out_x    = out;
    float* out_mask = out + out_size - 1 - M_;
    float* out_loss = out + out_size - 1;

    float *pq, *pk, *pv, *px2, *pimp, *pmsk;
    cudaGetSymbolAddress((void**)&pq,   g_q);
    cudaGetSymbolAddress((void**)&pk,   g_k);
    cudaGetSymbolAddress((void**)&pv,   g_v);
    cudaGetSymbolAddress((void**)&px2,  g_x2);
    cudaGetSymbolAddress((void**)&pimp, g_imp);
    cudaGetSymbolAddress((void**)&pmsk, g_msk);
    __half *ph16, *py16, *pf16, *pwat, *pwpr, *pwfc, *pwf2;
    cudaGetSymbolAddress((void**)&ph16, g_h16);
    cudaGetSymbolAddress((void**)&py16, g_y16);
    cudaGetSymbolAddress((void**)&pf16, g_f16);
    cudaGetSymbolAddress((void**)&pwat, g_wat);
    cudaGetSymbolAddress((void**)&pwpr, g_wpr);
    cudaGetSymbolAddress((void**)&pwfc, g_wfc);
    cudaGetSymbolAddress((void**)&pwf2, g_wf2);

    static int smem_set = 0;
    if (!smem_set) {
        cudaFuncSetAttribute(fattn_kernel,
                             cudaFuncAttributeMaxDynamicSharedMemorySize, FA_SMEM);
        cudaFuncSetAttribute(tgemm_kernel<0>,
                             cudaFuncAttributeMaxDynamicSharedMemorySize, GEMM_SMEM);
        cudaFuncSetAttribute(tgemm_kernel<1>,
                             cudaFuncAttributeMaxDynamicSharedMemorySize, GEMM_SMEM);
        cudaFuncSetAttribute(tgemm_kernel<2>,
                             cudaFuncAttributeMaxDynamicSharedMemorySize, GEMM_SMEM);
        cudaFuncSetAttribute(tgemm_kernel<3>,
                             cudaFuncAttributeMaxDynamicSharedMemorySize, GEMM_SMEM);
        smem_set = 1;
    }

    zero_kernel<<<16, 256>>>(pimp, M_);
    // weight transpose -> fp16 [N][K]
    wsplit_kernel<<<dim3(NQKV/32, C_/32), 256>>>(wattn, pwat, C_, NQKV);
    wsplit_kernel<<<dim3(C_/32,   C_/32), 256>>>(wproj, pwpr, C_, C_);
    wsplit_kernel<<<dim3(NFC/32,  C_/32), 256>>>(wfc,   pwfc, C_, NFC);
    wsplit_kernel<<<dim3(C_/32,  NFC/32), 256>>>(wfc2,  pwf2, NFC, C_);

    ln_kernel<<<M_, 256>>>(x, ln1w, ln1b, ph16);
    tgemm_kernel<0><<<dim3(NQKV/128, M_/128), 256, GEMM_SMEM>>>(
        ph16, pwat, battn, nullptr, nullptr, nullptr, M_, NQKV, C_);
    fattn_kernel<<<dim3(T_/QT, B_*H_), 512, FA_SMEM>>>(pq, pk, pv, am, py16, pimp);
    mask_kernel<<<16, 256>>>(pimp, am, thr, pmsk, out_mask, out_loss);
    tgemm_kernel<1><<<dim3(C_/128, M_/128), 256, GEMM_SMEM>>>(
        py16, pwpr, bproj, x, pmsk, px2, M_, C_, C_);
    ln_kernel<<<M_, 256>>>(px2, ln2w, ln2b, ph16);
    tgemm_kernel<2><<<dim3(NFC/128, M_/128), 256, GEMM_SMEM>>>(
        ph16, pwfc, bfc, nullptr, nullptr, nullptr, M_, NFC, C_);
    tgemm_kernel<3><<<dim3(C_/128, M_/128), 256, GEMM_SMEM>>>(
        pf16, pwf2, bfc2, px2, nullptr, out_x, M_, C_, NFC);
}